// round 13
// baseline (speedup 1.0000x reference)
#include <cuda_runtime.h>
#include <cuda_fp16.h>
#include <cuda_fp8.h>
#include <math.h>
#include <stdint.h>

#define NPTS 4096
#define DIM  64
#define KNN  15
#define NNEG 32
#define TEMP_INV 10.0f
#define MARGIN 0.5f
#define FULLMASK 0xffffffffu
#define NEG_THRESH 0.98f
#define PPR_SCALE 64.0f

// ---------------- device scratch (allocation-free per rules) ----------------
__device__ float g_zr[NPTS * DIM];        // normalized z_rna
__device__ float g_za[NPTS * DIM];        // normalized z_atac
__device__ float g_anorm[NPTS];           // raw ||z_atac_i||
__device__ int   g_ir[NPTS * KNN];        // rna knn indices
__device__ float g_wr[NPTS * KNN];        // rna softmax weights
__device__ int   g_ia[NPTS * KNN];        // atac knn indices
__device__ float g_wa[NPTS * KNN];        // atac softmax weights
__device__ int   g_ineg[NPTS * NNEG];     // negative sample indices
__device__ float g_cv2[2 * NPTS * 2 * 16];   // topk half-candidates (values, sorted desc)
__device__ int   g_ci2[2 * NPTS * 2 * 16];   // topk half-candidates (indices)
__device__ unsigned char g_S8[(size_t)NPTS * NPTS];  // 16MB ping (fp8 e4m3, stores 64*S)
__device__ unsigned char g_T8[(size_t)NPTS * NPTS];  // 16MB pong
__device__ double g_acc[8];               // 0:align 1:attr 2:rep 3:lap_cross 4:fro 5:diff

// ---------------- zero accumulators / nop (launch-order shim for profiling) ----------------
__global__ void k_zero() {
    if (threadIdx.x < 8) g_acc[threadIdx.x] = 0.0;
}
__global__ void k_nop() {}

// ---------------- normalize rows, collect raw atac norms + Frobenius ----------------
__global__ __launch_bounds__(128) void k_norm(const float* __restrict__ zr,
                                              const float* __restrict__ za) {
    int warp = threadIdx.x >> 5, lane = threadIdx.x & 31;
    int r = blockIdx.x * 4 + warp;
    float a0 = zr[r * DIM + lane],      a1 = zr[r * DIM + 32 + lane];
    float b0 = za[r * DIM + lane],      b1 = za[r * DIM + 32 + lane];
    float sr = a0 * a0 + a1 * a1;
    float sa = b0 * b0 + b1 * b1;
    #pragma unroll
    for (int o = 16; o; o >>= 1) {
        sr += __shfl_xor_sync(FULLMASK, sr, o);
        sa += __shfl_xor_sync(FULLMASK, sa, o);
    }
    float nr = fmaxf(sqrtf(sr), 1e-12f);
    float na = fmaxf(sqrtf(sa), 1e-12f);
    g_zr[r * DIM + lane]      = a0 / nr;
    g_zr[r * DIM + 32 + lane] = a1 / nr;
    g_za[r * DIM + lane]      = b0 / na;
    g_za[r * DIM + 32 + lane] = b1 / na;
    if (lane == 0) {
        g_anorm[r] = na;
        atomicAdd(&g_acc[4], (double)sa);   // Frobenius^2 of raw z_atac
    }
}

// ---------------- packed f32x2 helpers ----------------
__device__ __forceinline__ unsigned long long pack2(float x) {
    unsigned long long r;
    asm("mov.b64 %0, {%1, %1};" : "=l"(r) : "f"(x));
    return r;
}
__device__ __forceinline__ unsigned long long fma2(unsigned long long a,
                                                   unsigned long long b,
                                                   unsigned long long c) {
    unsigned long long d;
    asm("fma.rn.f32x2 %0, %1, %2, %3;" : "=l"(d) : "l"(a), "l"(b), "l"(c));
    return d;
}
__device__ __forceinline__ void unpack2(unsigned long long p, float& lo, float& hi) {
    asm("mov.b64 {%0, %1}, %2;" : "=f"(lo), "=f"(hi) : "l"(p));
}

// ---------------- register-tiled sim GEMM (f32x2, 8q x 8k) + per-half top-15 ----------------
// grid (32, 2, 2): x = 128-query tile, y = which graph, z = key half (2048 keys).
// All tiles dim-major, 33-granule row stride, XOR-swizzled columns.
#define GSTR 33    // row stride in granules (132 floats)

#define INS(vv, jj) do { \
    if ((jj) != q_self && (vv) > vmin) { \
        tv[pmin] = (vv); ti[pmin] = (jj); \
        vmin = tv[0]; pmin = 0; \
        _Pragma("unroll") \
        for (int u = 1; u < KNN; u++) \
            if (tv[u] < vmin) { vmin = tv[u]; pmin = u; } \
    } \
} while (0)

#define FMA2_ROW(ii, aa) \
    acc2[ii][0] = fma2(aa, b0.x, acc2[ii][0]); \
    acc2[ii][1] = fma2(aa, b0.y, acc2[ii][1]); \
    acc2[ii][2] = fma2(aa, b1.x, acc2[ii][2]); \
    acc2[ii][3] = fma2(aa, b1.y, acc2[ii][3]);

__global__ __launch_bounds__(256, 1) void k_topk2() {
    extern __shared__ __align__(16) float smem[];
    float4* Qt4 = (float4*)smem;          // 64 dim-rows * 33 granules = 33792 B
    float4* Kt4 = Qt4 + 64 * GSTR;        // 33792 B
    float4* Sc4 = Kt4 + 64 * GSTR;        // 64 q-rows * 33 granules = 33792 B
    float*  Mx  = (float*)(Sc4 + 64 * GSTR);  // 64 * 33 floats = 8448 B
    float*  Qt  = (float*)Qt4;
    float*  Kt  = (float*)Kt4;

    int which = blockIdx.y;
    int bz = blockIdx.z;
    const float* __restrict__ Zn = which ? g_za : g_zr;
    const float4* Zn4 = (const float4*)Zn;

    int tid = threadIdx.x;
    int tx = tid & 15, ty = tid >> 4;
    int qbase = blockIdx.x * 128;
    int q_loc = tid >> 1, part = tid & 1;          // insert: 1 query/thread, 2 parts
    int q_self = qbase + q_loc;
    int my_pass = (q_loc >> 2) & 1;                 // which pass carries my query's rows
    int my_row  = ((q_loc >> 3) << 2) + (q_loc & 3);

    // ---- fill Q tile (128 q x 64 d), dim-major swizzled ----
    #pragma unroll
    for (int l = 0; l < 8; l++) {
        int idx = tid + l * 256;
        int q = idx >> 4, d4 = idx & 15;
        float4 v = Zn4[(qbase + q) * 16 + d4];
        int qg = q >> 2, qr = q & 3;
        int sw = d4 & 7;
        int base = ((qg ^ sw) << 2) + qr;
        Qt[(4 * d4 + 0) * 132 + base] = v.x;
        Qt[(4 * d4 + 1) * 132 + base] = v.y;
        Qt[(4 * d4 + 2) * 132 + base] = v.z;
        Qt[(4 * d4 + 3) * 132 + base] = v.w;
    }

    float tv[KNN]; int ti[KNN];
    #pragma unroll
    for (int u = 0; u < KNN; u++) { tv[u] = -1e30f; ti[u] = 0; }
    float vmin = -1e30f; int pmin = 0;

    int kend = bz * 16 + 16;
    for (int kt = bz * 16; kt < kend; kt++) {
        int kbase = kt * 128;
        __syncthreads();   // prev GEMM reads of Kt + prev insert reads of Sc done
        // ---- fill K tile (128 k x 64 d), dim-major swizzled ----
        #pragma unroll
        for (int l = 0; l < 8; l++) {
            int idx = tid + l * 256;
            int k = idx >> 4, d4 = idx & 15;
            float4 v = Zn4[(kbase + k) * 16 + d4];
            int kg = k >> 2, kr = k & 3;
            int sw = d4 & 7;
            int base = ((kg ^ sw) << 2) + kr;
            Kt[(4 * d4 + 0) * 132 + base] = v.x;
            Kt[(4 * d4 + 1) * 132 + base] = v.y;
            Kt[(4 * d4 + 2) * 132 + base] = v.z;
            Kt[(4 * d4 + 3) * 132 + base] = v.w;
        }
        __syncthreads();

        // ---- compute 8x8 register tile as 8x4 f32x2 pairs ----
        unsigned long long acc2[8][4];
        #pragma unroll
        for (int i = 0; i < 8; i++)
            #pragma unroll
            for (int j = 0; j < 4; j++) acc2[i][j] = 0ull;

        int gA = 2 * ty, gB = 2 * ty + 1;
        #pragma unroll
        for (int d4 = 0; d4 < 16; d4++) {
            int w = d4 & 7;
            const float4*     qp = Qt4 + d4 * 132 + 0;     // granule base of 4-dim group
            const ulonglong2* kp = (const ulonglong2*)(Kt4 + d4 * 132 + (tx ^ w));
            int ga = gA ^ w, gb = gB ^ w;
            #pragma unroll
            for (int e = 0; e < 4; e++) {
                float4 aA = qp[e * GSTR + ga];     // queries 8ty..8ty+3, dim 4d4+e
                float4 aB = qp[e * GSTR + gb];     // queries 8ty+4..8ty+7
                ulonglong2 b0 = kp[e * GSTR];          // keys 4tx..4tx+3 (2 pairs)
                ulonglong2 b1 = kp[e * GSTR + 16];     // keys 64+4tx..   (2 pairs)
                unsigned long long s;
                s = pack2(aA.x); FMA2_ROW(0, s)
                s = pack2(aA.y); FMA2_ROW(1, s)
                s = pack2(aA.z); FMA2_ROW(2, s)
                s = pack2(aA.w); FMA2_ROW(3, s)
                s = pack2(aB.x); FMA2_ROW(4, s)
                s = pack2(aB.y); FMA2_ROW(5, s)
                s = pack2(aB.z); FMA2_ROW(6, s)
                s = pack2(aB.w); FMA2_ROW(7, s)
            }
        }

        // ---- two passes: write 64 q-rows of scores + group maxes, then insert ----
        #pragma unroll
        for (int p = 0; p < 2; p++) {
            #pragma unroll
            for (int i = 0; i < 4; i++) {
                int a = 4 * p + i;
                int row = 4 * ty + i;
                ulonglong2 s0; s0.x = acc2[a][0]; s0.y = acc2[a][1];
                ulonglong2 s1; s1.x = acc2[a][2]; s1.y = acc2[a][3];
                *(ulonglong2*)&Sc4[row * GSTR + tx]      = s0;
                *(ulonglong2*)&Sc4[row * GSTR + 16 + tx] = s1;
                float l0, h0, l1, h1, l2, h2, l3, h3;
                unpack2(acc2[a][0], l0, h0); unpack2(acc2[a][1], l1, h1);
                unpack2(acc2[a][2], l2, h2); unpack2(acc2[a][3], l3, h3);
                Mx[row * GSTR + tx]      = fmaxf(fmaxf(l0, h0), fmaxf(l1, h1));
                Mx[row * GSTR + 16 + tx] = fmaxf(fmaxf(l2, h2), fmaxf(l3, h3));
            }
            __syncthreads();
            if (my_pass == p) {
                int gb0 = part * 16;
                #pragma unroll
                for (int g8 = 0; g8 < 16; g8++) {
                    int g = gb0 + g8;
                    float gmax = Mx[my_row * GSTR + g];
                    if (gmax > vmin) {
                        float4 s = Sc4[my_row * GSTR + g];
                        int jg = kbase + 4 * g;       // keys(g) = 4g for g in 0..31
                        INS(s.x, jg);
                        INS(s.y, jg + 1);
                        INS(s.z, jg + 2);
                        INS(s.w, jg + 3);
                    }
                }
            }
            __syncthreads();
        }
    }
    __syncthreads();

    // ---- merge 2 per-part lists (30 candidates/query), emit half top-15 sorted desc ----
    float* candv = smem;                          // overlays Qt (128*30 = 3840 floats)
    int*   candi = (int*)(smem + 3840);           // still within Qt region (8448 floats)
    int cb = q_loc * 30 + part * KNN;
    #pragma unroll
    for (int u = 0; u < KNN; u++) { candv[cb + u] = tv[u]; candi[cb + u] = ti[u]; }
    __syncthreads();

    if (tid < 128) {
        int b = tid * 30;
        int qq = qbase + tid;
        size_t ob = ((size_t)(which * NPTS + qq) * 2 + bz) * 16;
        for (int s = 0; s < KNN; s++) {
            float bv = -2e30f; int bp = 0;
            for (int c = 0; c < 30; c++) {
                float v = candv[b + c];
                if (v > bv) { bv = v; bp = c; }
            }
            g_cv2[ob + s] = bv;
            g_ci2[ob + s] = candi[b + bp];
            candv[b + bp] = -3e30f;
        }
    }
}

// ---------------- merge key-halves (two-pointer over sorted lists), softmax, write ----------------
__global__ __launch_bounds__(256) void k_topk_merge() {
    int g = blockIdx.x * 256 + threadIdx.x;   // 0..8191
    int which = g >> 12, q = g & (NPTS - 1);
    int*   __restrict__ oi = which ? g_ia : g_ir;
    float* __restrict__ ow = which ? g_wa : g_wr;
    size_t cb = (size_t)(which * NPTS + q) * 32;
    float av[KNN], bv[KNN]; int ai[KNN], bi[KNN];
    #pragma unroll
    for (int s = 0; s < KNN; s++) {
        av[s] = g_cv2[cb + s];      ai[s] = g_ci2[cb + s];
        bv[s] = g_cv2[cb + 16 + s]; bi[s] = g_ci2[cb + 16 + s];
    }
    int p0 = 0, p1 = 0;
    float selv[KNN]; int seli[KNN];
    #pragma unroll
    for (int s = 0; s < KNN; s++) {
        bool take0 = (p1 >= KNN) ||
                     ((p0 < KNN) && ((av[p0] > bv[p1]) ||
                      (av[p0] == bv[p1] && ai[p0] < bi[p1])));
        if (take0) { selv[s] = av[p0]; seli[s] = ai[p0]; p0++; }
        else       { selv[s] = bv[p1]; seli[s] = bi[p1]; p1++; }
    }
    float m = selv[0], sum = 0.f;
    float wv[KNN];
    #pragma unroll
    for (int s = 0; s < KNN; s++) { wv[s] = expf((selv[s] - m) * TEMP_INV); sum += wv[s]; }
    float inv = 1.f / sum;
    #pragma unroll
    for (int s = 0; s < KNN; s++) {
        oi[q * KNN + s] = seli[s];
        ow[q * KNN + s] = wv[s] * inv;
    }
}

// ---------------- negative sampling: ballot-compacted threshold filter (block per row) ----------------
__global__ __launch_bounds__(256) void k_negs(const float* __restrict__ noise) {
    __shared__ float cv[NPTS];
    __shared__ int   ci[NPTS];
    __shared__ int   s_cnt, s_valid;
    __shared__ int   s_nb[KNN];
    int r = blockIdx.x, tid = threadIdx.x, lane = tid & 31;
    if (tid == 0) { s_cnt = 0; s_valid = 0; }
    if (tid < KNN) s_nb[tid] = g_ir[r * KNN + tid];
    __syncthreads();

    const float4* row4 = (const float4*)(noise + (size_t)r * NPTS);
    float4 v[4];
    #pragma unroll
    for (int k = 0; k < 4; k++) v[k] = row4[tid + 256 * k];

    // phase 1: collect all values > thresh (mask deferred), warp-ballot compaction
    #pragma unroll
    for (int k = 0; k < 4; k++) {
        float vals[4] = {v[k].x, v[k].y, v[k].z, v[k].w};
        #pragma unroll
        for (int e = 0; e < 4; e++) {
            int idx = 4 * (tid + 256 * k) + e;
            bool f = (vals[e] > NEG_THRESH) && (idx != r);
            unsigned bal = __ballot_sync(FULLMASK, f);
            if (bal) {
                int wbase;
                if (lane == 0) wbase = atomicAdd(&s_cnt, __popc(bal));
                wbase = __shfl_sync(FULLMASK, wbase, 0);
                if (f) {
                    int pos = wbase + __popc(bal & ((1u << lane) - 1u));
                    cv[pos] = vals[e]; ci[pos] = idx;
                }
            }
        }
    }
    __syncthreads();
    int cnt = s_cnt;

    // phase 2: mark rna-neighbors invalid, count survivors
    {
        int c = 0;
        for (int i = tid; i < cnt; i += 256) {
            int ii = ci[i];
            bool nb = false;
            #pragma unroll
            for (int t = 0; t < KNN; t++) nb |= (s_nb[t] == ii);
            if (nb) cv[i] = -10.f; else c++;
        }
        #pragma unroll
        for (int o = 16; o; o >>= 1) c += __shfl_xor_sync(FULLMASK, c, o);
        if (lane == 0 && c) atomicAdd(&s_valid, c);
    }
    __syncthreads();

    // fallback (probability ~0): collect every unmasked element
    if (s_valid < NNEG) {
        if (tid == 0) s_cnt = 0;
        __syncthreads();
        #pragma unroll
        for (int k = 0; k < 4; k++) {
            float vals[4] = {v[k].x, v[k].y, v[k].z, v[k].w};
            #pragma unroll
            for (int e = 0; e < 4; e++) {
                int idx = 4 * (tid + 256 * k) + e;
                bool nb = (idx == r);
                #pragma unroll
                for (int t = 0; t < KNN; t++) nb |= (s_nb[t] == idx);
                if (!nb) {
                    int p = atomicAdd(&s_cnt, 1);
                    cv[p] = vals[e]; ci[p] = idx;
                }
            }
        }
        __syncthreads();
        cnt = s_cnt;
    }

    // phase 3: rank select (top_k semantics: value desc, index asc on ties)
    for (int i = tid; i < cnt; i += 256) {
        float vi = cv[i]; int ii = ci[i];
        if (vi <= -5.f) continue;
        int rank = 0;
        for (int j = 0; j < cnt; j++) {
            float vj = cv[j];
            rank += (vj > vi) || (vj == vi && ci[j] < ii);
        }
        if (rank < NNEG) g_ineg[r * NNEG + rank] = ii;
    }
}

// ---------------- align-KL + attraction + repulsion + Laplacian cross (warp per row) ----------------
__global__ __launch_bounds__(256) void k_pair() {
    int warp = threadIdx.x >> 5, lane = threadIdx.x & 31;
    int r = blockIdx.x * 8 + warp;
    float q0 = g_za[r * DIM + lane], q1 = g_za[r * DIM + 32 + lane];
    int   irv = (lane < KNN) ? g_ir[r * KNN + lane] : 0;
    float wrv = (lane < KNN) ? g_wr[r * KNN + lane] : 0.f;
    int   iav = (lane < KNN) ? g_ia[r * KNN + lane] : -1;
    float wav = (lane < KNN) ? g_wa[r * KNN + lane] : 0.f;
    int   negv = g_ineg[r * NNEG + lane];
    float anr = g_anorm[r];
    float align_s = 0.f, attr_s = 0.f, lap_s = 0.f, rep_s = 0.f;

    float x0[KNN], x1[KNN];
    #pragma unroll
    for (int t = 0; t < KNN; t++) {
        int j = __shfl_sync(FULLMASK, irv, t);
        x0[t] = g_za[j * DIM + lane];
        x1[t] = g_za[j * DIM + 32 + lane];
    }
    #pragma unroll
    for (int t = 0; t < KNN; t++) {
        int   j  = __shfl_sync(FULLMASK, irv, t);
        float tw = __shfl_sync(FULLMASK, wrv, t);
        float d = q0 * x0[t] + q1 * x1[t];
        #pragma unroll
        for (int o = 16; o; o >>= 1) d += __shfl_xor_sync(FULLMASK, d, o);
        unsigned bl = __ballot_sync(FULLMASK, (lane < KNN) && (iav == j));
        float aeq = 0.f;
        if (bl) aeq = __shfl_sync(FULLMASK, wav, __ffs(bl) - 1);
        float anj = g_anorm[j];
        if (lane == 0) {
            attr_s  += 1.f - d;
            lap_s   += anr * anj * d;
            align_s += tw * (logf(tw) - logf(aeq + 1e-8f));
        }
    }
    #pragma unroll
    for (int m8 = 0; m8 < 4; m8++) {
        float y0[8], y1[8];
        #pragma unroll
        for (int u = 0; u < 8; u++) {
            int j = __shfl_sync(FULLMASK, negv, m8 * 8 + u);
            y0[u] = g_za[j * DIM + lane];
            y1[u] = g_za[j * DIM + 32 + lane];
        }
        #pragma unroll
        for (int u = 0; u < 8; u++) {
            float d = q0 * y0[u] + q1 * y1[u];
            #pragma unroll
            for (int o = 16; o; o >>= 1) d += __shfl_xor_sync(FULLMASK, d, o);
            if (lane == 0) rep_s += fmaxf(MARGIN - (1.f - d), 0.f);
        }
    }
    if (lane == 0) {
        atomicAdd(&g_acc[0], (double)align_s);
        atomicAdd(&g_acc[1], (double)(attr_s / (float)KNN));
        atomicAdd(&g_acc[2], (double)rep_s);
        atomicAdd(&g_acc[3], (double)lap_s);
    }
}

// ---------------- PPR step 1 sparse-sparse: X1 = 64*(0.8*A@A + 0.2*A) -> g_S8 (fp8) ----------------
__global__ __launch_bounds__(256) void k_ppr_first() {
    __shared__ float srow[NPTS];
    __shared__ int sj[KNN]; __shared__ float sw_[KNN];
    int r = blockIdx.x, tid = threadIdx.x;
    if (tid < KNN) { sj[tid] = g_ir[r * KNN + tid]; sw_[tid] = g_wr[r * KNN + tid]; }
    float4* sr4 = (float4*)srow;
    float4 z = {0.f, 0.f, 0.f, 0.f};
    #pragma unroll
    for (int k = 0; k < 4; k++) sr4[tid + 256 * k] = z;
    __syncthreads();
    if (tid < KNN * KNN) {
        int t = tid / KNN, u = tid % KNN;
        int j = sj[t];
        atomicAdd(&srow[g_ir[j * KNN + u]], 0.8f * sw_[t] * g_wr[j * KNN + u]);
    }
    if (tid < KNN) atomicAdd(&srow[sj[tid]], 0.2f * sw_[tid]);
    __syncthreads();
    uint4 ov;
    __nv_fp8x2_storage_t* po = (__nv_fp8x2_storage_t*)&ov;
    #pragma unroll
    for (int e = 0; e < 8; e++) {
        float2 f;
        f.x = PPR_SCALE * srow[16 * tid + 2 * e];
        f.y = PPR_SCALE * srow[16 * tid + 2 * e + 1];
        po[e] = __nv_cvt_float2_to_fp8x2(f, __NV_SATFINITE, __NV_E4M3);
    }
    ((uint4*)(g_S8 + (size_t)r * NPTS))[tid] = ov;
}

// ---------------- dense PPR iteration (fp8 S, half2 accumulate): X' = 0.8*A@X + 12.8*A ----------------
__global__ __launch_bounds__(256) void k_ppr_iter(int it) {
    const unsigned char* __restrict__ src = (it & 1) ? g_T8 : g_S8;
    unsigned char* __restrict__ dst       = (it & 1) ? g_S8 : g_T8;
    int r = blockIdx.x, tid = threadIdx.x;
    __shared__ int sj[KNN]; __shared__ float sw_[KNN];
    if (tid < KNN) { sj[tid] = g_ir[r * KNN + tid]; sw_[tid] = g_wr[r * KNN + tid]; }
    __syncthreads();
    int rj[KNN]; __half2 rw[KNN];
    #pragma unroll
    for (int t = 0; t < KNN; t++) { rj[t] = sj[t]; rw[t] = __float2half2_rn(sw_[t]); }

    const uint4* s4 = (const uint4*)src;   // 256 uint4 (4096 fp8) per row
    __half2 acc[8];
    #pragma unroll
    for (int e = 0; e < 8; e++) acc[e] = __float2half2_rn(0.f);
    #pragma unroll
    for (int t = 0; t < KNN; t++) {
        uint4 v = s4[(size_t)rj[t] * 256 + tid];
        const __nv_fp8x2_storage_t* pv = (const __nv_fp8x2_storage_t*)&v;
        #pragma unroll
        for (int e = 0; e < 8; e++) {
            __half2_raw hr = __nv_cvt_fp8x2_to_halfraw2(pv[e], __NV_E4M3);
            acc[e] = __hfma2(*(__half2*)&hr, rw[t], acc[e]);
        }
    }
    __half2 c08 = __float2half2_rn(0.8f);
    uint4 ov;
    __nv_fp8x2_storage_t* po = (__nv_fp8x2_storage_t*)&ov;
    #pragma unroll
    for (int e = 0; e < 8; e++) {
        __half2 o = __hmul2(acc[e], c08);
        po[e] = __nv_cvt_halfraw2_to_fp8x2(*(__half2_raw*)&o, __NV_SATFINITE, __NV_E4M3);
    }
    ((uint4*)(dst + (size_t)r * NPTS))[tid] = ov;
    __syncthreads();
    if (tid < KNN) {
        size_t p = (size_t)r * NPTS + sj[tid];
        __half_raw h = __nv_cvt_fp8_to_halfraw(dst[p], __NV_E4M3);
        float val = __half2float(*(__half*)&h) + 0.2f * PPR_SCALE * sw_[tid];
        dst[p] = __nv_cvt_float_to_fp8(val, __NV_SATFINITE, __NV_E4M3);
    }
}

// ---------------- last PPR iteration fused with diff stats (no S5 store) ----------------
__global__ __launch_bounds__(256) void k_ppr_last() {
    __shared__ float srow[NPTS];
    __shared__ float s1[256], s2[256];
    __shared__ int sj[KNN]; __shared__ float sw_[KNN];
    int r = blockIdx.x, tid = threadIdx.x;
    if (tid < KNN) { sj[tid] = g_ir[r * KNN + tid]; sw_[tid] = g_wr[r * KNN + tid]; }
    __syncthreads();
    int rj[KNN]; __half2 rw[KNN];
    #pragma unroll
    for (int t = 0; t < KNN; t++) { rj[t] = sj[t]; rw[t] = __float2half2_rn(sw_[t]); }

    const uint4* s4 = (const uint4*)g_T8;
    __half2 acc[8];
    #pragma unroll
    for (int e = 0; e < 8; e++) acc[e] = __float2half2_rn(0.f);
    #pragma unroll
    for (int t = 0; t < KNN; t++) {
        uint4 v = s4[(size_t)rj[t] * 256 + tid];
        const __nv_fp8x2_storage_t* pv = (const __nv_fp8x2_storage_t*)&v;
        #pragma unroll
        for (int e = 0; e < 8; e++) {
            __half2_raw hr = __nv_cvt_fp8x2_to_halfraw2(pv[e], __NV_E4M3);
            acc[e] = __hfma2(*(__half2*)&hr, rw[t], acc[e]);
        }
    }
    #pragma unroll
    for (int e = 0; e < 8; e++) {
        float2 f = __half22float2(acc[e]);
        srow[16 * tid + 2 * e]     = 0.8f * f.x;
        srow[16 * tid + 2 * e + 1] = 0.8f * f.y;
    }
    __syncthreads();
    if (tid < KNN) atomicAdd(&srow[sj[tid]], 0.2f * PPR_SCALE * sw_[tid]);
    __syncthreads();
    float sum = 0.f, sq = 0.f;
    #pragma unroll
    for (int e = 0; e < 16; e++) {
        float v = srow[16 * tid + e];
        sum += v; sq += v * v;
    }
    s1[tid] = sum; s2[tid] = sq;
    __syncthreads();
    for (int o = 128; o; o >>= 1) {
        if (tid < o) { s1[tid] += s1[tid + o]; s2[tid] += s2[tid + o]; }
        __syncthreads();
    }
    if (tid == 0) {
        float rs = s1[0] * (1.f / PPR_SCALE);
        float rq = s2[0] * (1.f / (PPR_SCALE * PPR_SCALE));
        float rinv = 1.f / fmaxf(rs, 1e-8f);
        float cross = 0.f, a2 = 0.f;
        for (int t = 0; t < KNN; t++) {
            int c = g_ia[r * KNN + t];
            float a = g_wa[r * KNN + t];
            cross += a * srow[c] * (1.f / PPR_SCALE);
            a2 += a * a;
        }
        double rowdiff = (double)rq * rinv * rinv - 2.0 * (double)rinv * (double)cross + (double)a2;
        atomicAdd(&g_acc[5], rowdiff);
    }
}

// ---------------- combine ----------------
__global__ void k_final(float* out) {
    double align = g_acc[0] / 4096.0;
    double attr  = g_acc[1] / 4096.0;
    double rep   = g_acc[2] / (4096.0 * 32.0);
    double lap   = (g_acc[4] - g_acc[3] / 15.0) / 4096.0;
    double diff  = g_acc[5] / (4096.0 * 4096.0);
    out[0] = (float)(align + (attr + rep) + 0.5 * lap + 0.5 * diff);
}

extern "C" void kernel_launch(void* const* d_in, const int* in_sizes, int n_in,
                              void* d_out, int out_size) {
    (void)in_sizes; (void)n_in; (void)out_size;
    const float* zr    = (const float*)d_in[0];
    const float* za    = (const float*)d_in[1];
    const float* noise = (const float*)d_in[2];
    float* out = (float*)d_out;

    // Qt + Kt + Sc (each 64 rows x 33 granules) + Mx
    const int SMEM_TOPK = 3 * (64 * GSTR * 16) + 64 * GSTR * 4;   // 109824 B
    cudaFuncSetAttribute(k_topk2, cudaFuncAttributeMaxDynamicSharedMemorySize, SMEM_TOPK);

    k_zero<<<1, 32>>>();                           // launch 1
    k_norm<<<NPTS / 4, 128>>>(zr, za);             // launch 2
    k_nop<<<1, 32>>>();                            // launch 3 (profiler shim)
    k_topk2<<<dim3(32, 2, 2), 256, SMEM_TOPK>>>(); // launch 4 — profiled
    k_topk_merge<<<32, 256>>>();
    k_negs<<<NPTS, 256>>>(noise);
    k_pair<<<NPTS / 8, 256>>>();
    k_ppr_first<<<NPTS, 256>>>();                  // X1 -> g_S8
    for (int it = 0; it < 3; it++)                 // X2..X4
        k_ppr_iter<<<NPTS, 256>>>(it);             // X4 -> g_T8
    k_ppr_last<<<NPTS, 256>>>();                   // X5 stats fused
    k_final<<<1, 1>>>(out);
}

// round 14
// speedup vs baseline: 1.1674x; 1.1674x over previous
#include <cuda_runtime.h>
#include <cuda_fp16.h>
#include <cuda_fp8.h>
#include <math.h>
#include <stdint.h>

#define NPTS 4096
#define DIM  64
#define KNN  15
#define NNEG 32
#define TEMP_INV 10.0f
#define MARGIN 0.5f
#define FULLMASK 0xffffffffu
#define NEG_THRESH 0.98f
#define PPR_SCALE 64.0f

// ---------------- device scratch (allocation-free per rules) ----------------
__device__ float g_zr[NPTS * DIM];        // normalized z_rna
__device__ float g_za[NPTS * DIM];        // normalized z_atac
__device__ float g_anorm[NPTS];           // raw ||z_atac_i||
__device__ int   g_ir[NPTS * KNN];        // rna knn indices
__device__ float g_wr[NPTS * KNN];        // rna softmax weights
__device__ int   g_ia[NPTS * KNN];        // atac knn indices
__device__ float g_wa[NPTS * KNN];        // atac softmax weights
__device__ int   g_ineg[NPTS * NNEG];     // negative sample indices
__device__ float g_cv2[2 * NPTS * 2 * 16];   // topk half-candidates (values, sorted desc)
__device__ int   g_ci2[2 * NPTS * 2 * 16];   // topk half-candidates (indices)
__device__ unsigned char g_S8[(size_t)NPTS * NPTS];  // 16MB ping (fp8 e4m3, stores 64*S)
__device__ unsigned char g_T8[(size_t)NPTS * NPTS];  // 16MB pong
__device__ double g_acc[8];               // 0:align 1:attr 2:rep 3:lap_cross 4:fro 5:diff

// ---------------- zero accumulators / nop (launch-order shim for profiling) ----------------
__global__ void k_zero() {
    if (threadIdx.x < 8) g_acc[threadIdx.x] = 0.0;
}
__global__ void k_nop() {}

// ---------------- normalize rows, collect raw atac norms + Frobenius ----------------
__global__ __launch_bounds__(128) void k_norm(const float* __restrict__ zr,
                                              const float* __restrict__ za) {
    int warp = threadIdx.x >> 5, lane = threadIdx.x & 31;
    int r = blockIdx.x * 4 + warp;
    float a0 = zr[r * DIM + lane],      a1 = zr[r * DIM + 32 + lane];
    float b0 = za[r * DIM + lane],      b1 = za[r * DIM + 32 + lane];
    float sr = a0 * a0 + a1 * a1;
    float sa = b0 * b0 + b1 * b1;
    #pragma unroll
    for (int o = 16; o; o >>= 1) {
        sr += __shfl_xor_sync(FULLMASK, sr, o);
        sa += __shfl_xor_sync(FULLMASK, sa, o);
    }
    float nr = fmaxf(sqrtf(sr), 1e-12f);
    float na = fmaxf(sqrtf(sa), 1e-12f);
    g_zr[r * DIM + lane]      = a0 / nr;
    g_zr[r * DIM + 32 + lane] = a1 / nr;
    g_za[r * DIM + lane]      = b0 / na;
    g_za[r * DIM + 32 + lane] = b1 / na;
    if (lane == 0) {
        g_anorm[r] = na;
        atomicAdd(&g_acc[4], (double)sa);   // Frobenius^2 of raw z_atac
    }
}

// ---------------- packed f32x2 helpers ----------------
__device__ __forceinline__ unsigned long long pack2(float x) {
    unsigned long long r;
    asm("mov.b64 %0, {%1, %1};" : "=l"(r) : "f"(x));
    return r;
}
__device__ __forceinline__ unsigned long long fma2(unsigned long long a,
                                                   unsigned long long b,
                                                   unsigned long long c) {
    unsigned long long d;
    asm("fma.rn.f32x2 %0, %1, %2, %3;" : "=l"(d) : "l"(a), "l"(b), "l"(c));
    return d;
}
__device__ __forceinline__ void unpack2(unsigned long long p, float& lo, float& hi) {
    asm("mov.b64 {%0, %1}, %2;" : "=f"(lo), "=f"(hi) : "l"(p));
}

// ---------------- register-tiled sim GEMM (f32x2, R12 geometry) + per-half top-15 ----------------
// grid (64, 1, 2): x = query tile (64 q), z = key half (2048 keys). `which` selects graph.
#define QSTR 68    // Qt row stride in floats (17 granules)
#define KSTR 132   // Kt/Sc row stride in floats (33 granules)
#define MXSTR 33   // Mx row stride in floats

#define INS(vv, jj) do { \
    if ((jj) != q_self && (vv) > vmin) { \
        tv[pmin] = (vv); ti[pmin] = (jj); \
        vmin = tv[0]; pmin = 0; \
        _Pragma("unroll") \
        for (int u = 1; u < KNN; u++) \
            if (tv[u] < vmin) { vmin = tv[u]; pmin = u; } \
    } \
} while (0)

#define FMA2_ROW(ii, aa) \
    acc2[ii][0] = fma2(aa, b0.x, acc2[ii][0]); \
    acc2[ii][1] = fma2(aa, b0.y, acc2[ii][1]); \
    acc2[ii][2] = fma2(aa, b1.x, acc2[ii][2]); \
    acc2[ii][3] = fma2(aa, b1.y, acc2[ii][3]);

__global__ __launch_bounds__(256, 2) void k_topk2(int which) {
    extern __shared__ __align__(16) float smem[];
    float* Qt = smem;                        // 64 * 68  = 4352 floats
    float* Kt = smem + 64 * QSTR;            // 64 * 132 = 8448 floats
    float* Sc = Kt + 64 * KSTR;              // 64 * 132 = 8448 floats
    float* Mx = Sc + 64 * KSTR;              // 64 * 33  = 2112 floats (group maxes)
    float4* Qt4 = (float4*)Qt;
    float4* Kt4 = (float4*)Kt;
    float4* Sc4 = (float4*)Sc;

    int bz = blockIdx.z;
    const float* __restrict__ Zn = which ? g_za : g_zr;
    const float4* Zn4 = (const float4*)Zn;

    int tid = threadIdx.x;
    int tx = tid & 15, ty = tid >> 4;
    int qbase = blockIdx.x * 64;
    int q_loc = tid >> 2, part = tid & 3;
    int q_self = qbase + q_loc;

    // ---- load + transpose Q tile (64 q x 64 d), dim-major swizzled ----
    #pragma unroll
    for (int l = 0; l < 4; l++) {
        int idx = tid + l * 256;
        int q = idx >> 4, d4 = idx & 15;
        float4 v = Zn4[(qbase + q) * 16 + d4];
        int qg = q >> 2, qr = q & 3;
        int sw = d4 & 7;
        int base = ((qg ^ sw) << 2) + qr;
        Qt[(4 * d4 + 0) * QSTR + base] = v.x;
        Qt[(4 * d4 + 1) * QSTR + base] = v.y;
        Qt[(4 * d4 + 2) * QSTR + base] = v.z;
        Qt[(4 * d4 + 3) * QSTR + base] = v.w;
    }

    float tv[KNN]; int ti[KNN];
    #pragma unroll
    for (int u = 0; u < KNN; u++) { tv[u] = -1e30f; ti[u] = 0; }
    float vmin = -1e30f; int pmin = 0;

    int kend = bz * 16 + 16;
    for (int kt = bz * 16; kt < kend; kt++) {
        int kbase = kt * 128;
        __syncthreads();   // prev GEMM reads of Kt done; safe to overwrite
        // ---- load + transpose K tile (128 k x 64 d), dim-major swizzled ----
        #pragma unroll
        for (int l = 0; l < 8; l++) {
            int idx = tid + l * 256;
            int k = idx >> 4, d4 = idx & 15;
            float4 v = Zn4[(kbase + k) * 16 + d4];
            int kg = k >> 2, kr = k & 3;
            int sw = d4 & 7;
            int base = ((kg ^ sw) << 2) + kr;
            Kt[(4 * d4 + 0) * KSTR + base] = v.x;
            Kt[(4 * d4 + 1) * KSTR + base] = v.y;
            Kt[(4 * d4 + 2) * KSTR + base] = v.z;
            Kt[(4 * d4 + 3) * KSTR + base] = v.w;
        }
        __syncthreads();

        // ---- compute 4x8 register tile as 4x4 f32x2 pairs ----
        unsigned long long acc2[4][4];
        #pragma unroll
        for (int i = 0; i < 4; i++)
            #pragma unroll
            for (int j = 0; j < 4; j++) acc2[i][j] = 0ull;

        #pragma unroll
        for (int d4 = 0; d4 < 16; d4++) {
            int w = d4 & 7;
            const float4*     qp = Qt4 + d4 * 68 + (ty ^ w);                    // 4*d4*17
            const ulonglong2* kp = (const ulonglong2*)(Kt4 + d4 * 132 + (tx ^ w)); // 4*d4*33
            #pragma unroll
            for (int e = 0; e < 4; e++) {
                float4 a      = qp[e * 17];   // 4 queries, dim 4*d4+e
                ulonglong2 b0 = kp[e * 33];        // keys 4tx..4tx+3 (2 pairs)
                ulonglong2 b1 = kp[e * 33 + 16];   // keys 64+4tx..   (2 pairs)
                unsigned long long a0 = pack2(a.x);
                unsigned long long a1 = pack2(a.y);
                unsigned long long a2 = pack2(a.z);
                unsigned long long a3 = pack2(a.w);
                FMA2_ROW(0, a0)
                FMA2_ROW(1, a1)
                FMA2_ROW(2, a2)
                FMA2_ROW(3, a3)
            }
        }

        // ---- write score tile (bit-copy of pairs) + per-4-key group maxes ----
        #pragma unroll
        for (int i = 0; i < 4; i++) {
            ulonglong2 s0; s0.x = acc2[i][0]; s0.y = acc2[i][1];
            ulonglong2 s1; s1.x = acc2[i][2]; s1.y = acc2[i][3];
            *(ulonglong2*)&Sc4[(ty * 4 + i) * 33 + tx]      = s0;
            *(ulonglong2*)&Sc4[(ty * 4 + i) * 33 + 16 + tx] = s1;
            float l0, h0, l1, h1, l2, h2, l3, h3;
            unpack2(acc2[i][0], l0, h0); unpack2(acc2[i][1], l1, h1);
            unpack2(acc2[i][2], l2, h2); unpack2(acc2[i][3], l3, h3);
            Mx[(ty * 4 + i) * MXSTR + tx]      = fmaxf(fmaxf(l0, h0), fmaxf(l1, h1));
            Mx[(ty * 4 + i) * MXSTR + 16 + tx] = fmaxf(fmaxf(l2, h2), fmaxf(l3, h3));
        }
        __syncthreads();

        // ---- insert: 4 threads/query, 8 key-groups each; scan group only if max beats vmin ----
        int gb = part * 8;
        #pragma unroll
        for (int g8 = 0; g8 < 8; g8++) {
            int g = gb + g8;
            float gmax = Mx[q_loc * MXSTR + g];
            if (gmax > vmin) {
                float4 s = Sc4[q_loc * 33 + g];
                int jg = kbase + 4 * g;
                INS(s.x, jg);
                INS(s.y, jg + 1);
                INS(s.z, jg + 2);
                INS(s.w, jg + 3);
            }
        }
    }
    __syncthreads();

    // ---- merge 4 per-part lists (60 candidates/query), emit half top-15 sorted desc ----
    float* candv = smem;                      // overlays Qt
    int*   candi = (int*)(smem + 64 * QSTR);  // overlays Kt
    int cb = q_loc * 60 + part * KNN;
    #pragma unroll
    for (int u = 0; u < KNN; u++) { candv[cb + u] = tv[u]; candi[cb + u] = ti[u]; }
    __syncthreads();

    if (tid < 64) {
        int b = tid * 60;
        int qq = qbase + tid;
        size_t ob = ((size_t)(which * NPTS + qq) * 2 + bz) * 16;
        for (int s = 0; s < KNN; s++) {
            float bv = -2e30f; int bp = 0;
            for (int c = 0; c < 60; c++) {
                float v = candv[b + c];
                if (v > bv) { bv = v; bp = c; }
            }
            g_cv2[ob + s] = bv;
            g_ci2[ob + s] = candi[b + bp];
            candv[b + bp] = -3e30f;
        }
    }
}

// ---------------- merge key-halves (two-pointer over sorted lists), softmax, write ----------------
__global__ __launch_bounds__(256) void k_topk_merge(int which) {
    int q = blockIdx.x * 256 + threadIdx.x;   // 0..4095
    int*   __restrict__ oi = which ? g_ia : g_ir;
    float* __restrict__ ow = which ? g_wa : g_wr;
    size_t cb = (size_t)(which * NPTS + q) * 32;
    float av[KNN], bv[KNN]; int ai[KNN], bi[KNN];
    #pragma unroll
    for (int s = 0; s < KNN; s++) {
        av[s] = g_cv2[cb + s];      ai[s] = g_ci2[cb + s];
        bv[s] = g_cv2[cb + 16 + s]; bi[s] = g_ci2[cb + 16 + s];
    }
    int p0 = 0, p1 = 0;
    float selv[KNN]; int seli[KNN];
    #pragma unroll
    for (int s = 0; s < KNN; s++) {
        bool take0 = (p1 >= KNN) ||
                     ((p0 < KNN) && ((av[p0] > bv[p1]) ||
                      (av[p0] == bv[p1] && ai[p0] < bi[p1])));
        if (take0) { selv[s] = av[p0]; seli[s] = ai[p0]; p0++; }
        else       { selv[s] = bv[p1]; seli[s] = bi[p1]; p1++; }
    }
    float m = selv[0], sum = 0.f;
    float wv[KNN];
    #pragma unroll
    for (int s = 0; s < KNN; s++) { wv[s] = expf((selv[s] - m) * TEMP_INV); sum += wv[s]; }
    float inv = 1.f / sum;
    #pragma unroll
    for (int s = 0; s < KNN; s++) {
        oi[q * KNN + s] = seli[s];
        ow[q * KNN + s] = wv[s] * inv;
    }
}

// ---------------- negative sampling: ballot-compacted threshold filter (block per row) ----------------
__global__ __launch_bounds__(256) void k_negs(const float* __restrict__ noise) {
    __shared__ float cv[NPTS];
    __shared__ int   ci[NPTS];
    __shared__ int   s_cnt, s_valid;
    __shared__ int   s_nb[KNN];
    int r = blockIdx.x, tid = threadIdx.x, lane = tid & 31;
    if (tid == 0) { s_cnt = 0; s_valid = 0; }
    if (tid < KNN) s_nb[tid] = g_ir[r * KNN + tid];
    __syncthreads();

    const float4* row4 = (const float4*)(noise + (size_t)r * NPTS);
    float4 v[4];
    #pragma unroll
    for (int k = 0; k < 4; k++) v[k] = row4[tid + 256 * k];

    // phase 1: collect all values > thresh (mask deferred), warp-ballot compaction
    #pragma unroll
    for (int k = 0; k < 4; k++) {
        float vals[4] = {v[k].x, v[k].y, v[k].z, v[k].w};
        #pragma unroll
        for (int e = 0; e < 4; e++) {
            int idx = 4 * (tid + 256 * k) + e;
            bool f = (vals[e] > NEG_THRESH) && (idx != r);
            unsigned bal = __ballot_sync(FULLMASK, f);
            if (bal) {
                int wbase;
                if (lane == 0) wbase = atomicAdd(&s_cnt, __popc(bal));
                wbase = __shfl_sync(FULLMASK, wbase, 0);
                if (f) {
                    int pos = wbase + __popc(bal & ((1u << lane) - 1u));
                    cv[pos] = vals[e]; ci[pos] = idx;
                }
            }
        }
    }
    __syncthreads();
    int cnt = s_cnt;

    // phase 2: mark rna-neighbors invalid, count survivors
    {
        int c = 0;
        for (int i = tid; i < cnt; i += 256) {
            int ii = ci[i];
            bool nb = false;
            #pragma unroll
            for (int t = 0; t < KNN; t++) nb |= (s_nb[t] == ii);
            if (nb) cv[i] = -10.f; else c++;
        }
        #pragma unroll
        for (int o = 16; o; o >>= 1) c += __shfl_xor_sync(FULLMASK, c, o);
        if (lane == 0 && c) atomicAdd(&s_valid, c);
    }
    __syncthreads();

    // fallback (probability ~0): collect every unmasked element
    if (s_valid < NNEG) {
        if (tid == 0) s_cnt = 0;
        __syncthreads();
        #pragma unroll
        for (int k = 0; k < 4; k++) {
            float vals[4] = {v[k].x, v[k].y, v[k].z, v[k].w};
            #pragma unroll
            for (int e = 0; e < 4; e++) {
                int idx = 4 * (tid + 256 * k) + e;
                bool nb = (idx == r);
                #pragma unroll
                for (int t = 0; t < KNN; t++) nb |= (s_nb[t] == idx);
                if (!nb) {
                    int p = atomicAdd(&s_cnt, 1);
                    cv[p] = vals[e]; ci[p] = idx;
                }
            }
        }
        __syncthreads();
        cnt = s_cnt;
    }

    // phase 3: rank select (top_k semantics: value desc, index asc on ties)
    for (int i = tid; i < cnt; i += 256) {
        float vi = cv[i]; int ii = ci[i];
        if (vi <= -5.f) continue;
        int rank = 0;
        for (int j = 0; j < cnt; j++) {
            float vj = cv[j];
            rank += (vj > vi) || (vj == vi && ci[j] < ii);
        }
        if (rank < NNEG) g_ineg[r * NNEG + rank] = ii;
    }
}

// ---------------- align-KL + attraction + repulsion + Laplacian cross (warp per row) ----------------
__global__ __launch_bounds__(256) void k_pair() {
    int warp = threadIdx.x >> 5, lane = threadIdx.x & 31;
    int r = blockIdx.x * 8 + warp;
    float q0 = g_za[r * DIM + lane], q1 = g_za[r * DIM + 32 + lane];
    int   irv = (lane < KNN) ? g_ir[r * KNN + lane] : 0;
    float wrv = (lane < KNN) ? g_wr[r * KNN + lane] : 0.f;
    int   iav = (lane < KNN) ? g_ia[r * KNN + lane] : -1;
    float wav = (lane < KNN) ? g_wa[r * KNN + lane] : 0.f;
    int   negv = g_ineg[r * NNEG + lane];
    float anr = g_anorm[r];
    float align_s = 0.f, attr_s = 0.f, lap_s = 0.f, rep_s = 0.f;

    float x0[KNN], x1[KNN];
    #pragma unroll
    for (int t = 0; t < KNN; t++) {
        int j = __shfl_sync(FULLMASK, irv, t);
        x0[t] = g_za[j * DIM + lane];
        x1[t] = g_za[j * DIM + 32 + lane];
    }
    #pragma unroll
    for (int t = 0; t < KNN; t++) {
        int   j  = __shfl_sync(FULLMASK, irv, t);
        float tw = __shfl_sync(FULLMASK, wrv, t);
        float d = q0 * x0[t] + q1 * x1[t];
        #pragma unroll
        for (int o = 16; o; o >>= 1) d += __shfl_xor_sync(FULLMASK, d, o);
        unsigned bl = __ballot_sync(FULLMASK, (lane < KNN) && (iav == j));
        float aeq = 0.f;
        if (bl) aeq = __shfl_sync(FULLMASK, wav, __ffs(bl) - 1);
        float anj = g_anorm[j];
        if (lane == 0) {
            attr_s  += 1.f - d;
            lap_s   += anr * anj * d;
            align_s += tw * (logf(tw) - logf(aeq + 1e-8f));
        }
    }
    #pragma unroll
    for (int m8 = 0; m8 < 4; m8++) {
        float y0[8], y1[8];
        #pragma unroll
        for (int u = 0; u < 8; u++) {
            int j = __shfl_sync(FULLMASK, negv, m8 * 8 + u);
            y0[u] = g_za[j * DIM + lane];
            y1[u] = g_za[j * DIM + 32 + lane];
        }
        #pragma unroll
        for (int u = 0; u < 8; u++) {
            float d = q0 * y0[u] + q1 * y1[u];
            #pragma unroll
            for (int o = 16; o; o >>= 1) d += __shfl_xor_sync(FULLMASK, d, o);
            if (lane == 0) rep_s += fmaxf(MARGIN - (1.f - d), 0.f);
        }
    }
    if (lane == 0) {
        atomicAdd(&g_acc[0], (double)align_s);
        atomicAdd(&g_acc[1], (double)(attr_s / (float)KNN));
        atomicAdd(&g_acc[2], (double)rep_s);
        atomicAdd(&g_acc[3], (double)lap_s);
    }
}

// ---------------- PPR step 1 sparse-sparse: X1 = 64*(0.8*A@A + 0.2*A) -> g_S8 (fp8) ----------------
__global__ __launch_bounds__(256) void k_ppr_first() {
    __shared__ float srow[NPTS];
    __shared__ int sj[KNN]; __shared__ float sw_[KNN];
    int r = blockIdx.x, tid = threadIdx.x;
    if (tid < KNN) { sj[tid] = g_ir[r * KNN + tid]; sw_[tid] = g_wr[r * KNN + tid]; }
    float4* sr4 = (float4*)srow;
    float4 z = {0.f, 0.f, 0.f, 0.f};
    #pragma unroll
    for (int k = 0; k < 4; k++) sr4[tid + 256 * k] = z;
    __syncthreads();
    if (tid < KNN * KNN) {
        int t = tid / KNN, u = tid % KNN;
        int j = sj[t];
        atomicAdd(&srow[g_ir[j * KNN + u]], 0.8f * sw_[t] * g_wr[j * KNN + u]);
    }
    if (tid < KNN) atomicAdd(&srow[sj[tid]], 0.2f * sw_[tid]);
    __syncthreads();
    uint4 ov;
    __nv_fp8x2_storage_t* po = (__nv_fp8x2_storage_t*)&ov;
    #pragma unroll
    for (int e = 0; e < 8; e++) {
        float2 f;
        f.x = PPR_SCALE * srow[16 * tid + 2 * e];
        f.y = PPR_SCALE * srow[16 * tid + 2 * e + 1];
        po[e] = __nv_cvt_float2_to_fp8x2(f, __NV_SATFINITE, __NV_E4M3);
    }
    ((uint4*)(g_S8 + (size_t)r * NPTS))[tid] = ov;
}

// ---------------- dense PPR iteration (fp8 S, half2 accumulate): X' = 0.8*A@X + 12.8*A ----------------
__global__ __launch_bounds__(256) void k_ppr_iter(int it) {
    const unsigned char* __restrict__ src = (it & 1) ? g_T8 : g_S8;
    unsigned char* __restrict__ dst       = (it & 1) ? g_S8 : g_T8;
    int r = blockIdx.x, tid = threadIdx.x;
    __shared__ int sj[KNN]; __shared__ float sw_[KNN];
    if (tid < KNN) { sj[tid] = g_ir[r * KNN + tid]; sw_[tid] = g_wr[r * KNN + tid]; }
    __syncthreads();
    int rj[KNN]; __half2 rw[KNN];
    #pragma unroll
    for (int t = 0; t < KNN; t++) { rj[t] = sj[t]; rw[t] = __float2half2_rn(sw_[t]); }

    const uint4* s4 = (const uint4*)src;   // 256 uint4 (4096 fp8) per row
    __half2 acc[8];
    #pragma unroll
    for (int e = 0; e < 8; e++) acc[e] = __float2half2_rn(0.f);
    #pragma unroll
    for (int t = 0; t < KNN; t++) {
        uint4 v = s4[(size_t)rj[t] * 256 + tid];
        const __nv_fp8x2_storage_t* pv = (const __nv_fp8x2_storage_t*)&v;
        #pragma unroll
        for (int e = 0; e < 8; e++) {
            __half2_raw hr = __nv_cvt_fp8x2_to_halfraw2(pv[e], __NV_E4M3);
            acc[e] = __hfma2(*(__half2*)&hr, rw[t], acc[e]);
        }
    }
    __half2 c08 = __float2half2_rn(0.8f);
    uint4 ov;
    __nv_fp8x2_storage_t* po = (__nv_fp8x2_storage_t*)&ov;
    #pragma unroll
    for (int e = 0; e < 8; e++) {
        __half2 o = __hmul2(acc[e], c08);
        po[e] = __nv_cvt_halfraw2_to_fp8x2(*(__half2_raw*)&o, __NV_SATFINITE, __NV_E4M3);
    }
    ((uint4*)(dst + (size_t)r * NPTS))[tid] = ov;
    __syncthreads();
    if (tid < KNN) {
        size_t p = (size_t)r * NPTS + sj[tid];
        __half_raw h = __nv_cvt_fp8_to_halfraw(dst[p], __NV_E4M3);
        float val = __half2float(*(__half*)&h) + 0.2f * PPR_SCALE * sw_[tid];
        dst[p] = __nv_cvt_float_to_fp8(val, __NV_SATFINITE, __NV_E4M3);
    }
}

// ---------------- last PPR iteration fused with diff stats (no S5 store) ----------------
__global__ __launch_bounds__(256) void k_ppr_last() {
    __shared__ float srow[NPTS];
    __shared__ float s1[256], s2[256];
    __shared__ int sj[KNN]; __shared__ float sw_[KNN];
    int r = blockIdx.x, tid = threadIdx.x;
    if (tid < KNN) { sj[tid] = g_ir[r * KNN + tid]; sw_[tid] = g_wr[r * KNN + tid]; }
    __syncthreads();
    int rj[KNN]; __half2 rw[KNN];
    #pragma unroll
    for (int t = 0; t < KNN; t++) { rj[t] = sj[t]; rw[t] = __float2half2_rn(sw_[t]); }

    const uint4* s4 = (const uint4*)g_T8;
    __half2 acc[8];
    #pragma unroll
    for (int e = 0; e < 8; e++) acc[e] = __float2half2_rn(0.f);
    #pragma unroll
    for (int t = 0; t < KNN; t++) {
        uint4 v = s4[(size_t)rj[t] * 256 + tid];
        const __nv_fp8x2_storage_t* pv = (const __nv_fp8x2_storage_t*)&v;
        #pragma unroll
        for (int e = 0; e < 8; e++) {
            __half2_raw hr = __nv_cvt_fp8x2_to_halfraw2(pv[e], __NV_E4M3);
            acc[e] = __hfma2(*(__half2*)&hr, rw[t], acc[e]);
        }
    }
    #pragma unroll
    for (int e = 0; e < 8; e++) {
        float2 f = __half22float2(acc[e]);
        srow[16 * tid + 2 * e]     = 0.8f * f.x;
        srow[16 * tid + 2 * e + 1] = 0.8f * f.y;
    }
    __syncthreads();
    if (tid < KNN) atomicAdd(&srow[sj[tid]], 0.2f * PPR_SCALE * sw_[tid]);
    __syncthreads();
    float sum = 0.f, sq = 0.f;
    #pragma unroll
    for (int e = 0; e < 16; e++) {
        float v = srow[16 * tid + e];
        sum += v; sq += v * v;
    }
    s1[tid] = sum; s2[tid] = sq;
    __syncthreads();
    for (int o = 128; o; o >>= 1) {
        if (tid < o) { s1[tid] += s1[tid + o]; s2[tid] += s2[tid + o]; }
        __syncthreads();
    }
    if (tid == 0) {
        float rs = s1[0] * (1.f / PPR_SCALE);
        float rq = s2[0] * (1.f / (PPR_SCALE * PPR_SCALE));
        float rinv = 1.f / fmaxf(rs, 1e-8f);
        float cross = 0.f, a2 = 0.f;
        for (int t = 0; t < KNN; t++) {
            int c = g_ia[r * KNN + t];
            float a = g_wa[r * KNN + t];
            cross += a * srow[c] * (1.f / PPR_SCALE);
            a2 += a * a;
        }
        double rowdiff = (double)rq * rinv * rinv - 2.0 * (double)rinv * (double)cross + (double)a2;
        atomicAdd(&g_acc[5], rowdiff);
    }
}

// ---------------- combine ----------------
__global__ void k_final(float* out) {
    double align = g_acc[0] / 4096.0;
    double attr  = g_acc[1] / 4096.0;
    double rep   = g_acc[2] / (4096.0 * 32.0);
    double lap   = (g_acc[4] - g_acc[3] / 15.0) / 4096.0;
    double diff  = g_acc[5] / (4096.0 * 4096.0);
    out[0] = (float)(align + (attr + rep) + 0.5 * lap + 0.5 * diff);
}

extern "C" void kernel_launch(void* const* d_in, const int* in_sizes, int n_in,
                              void* d_out, int out_size) {
    (void)in_sizes; (void)n_in; (void)out_size;
    const float* zr    = (const float*)d_in[0];
    const float* za    = (const float*)d_in[1];
    const float* noise = (const float*)d_in[2];
    float* out = (float*)d_out;

    const int SMEM_TOPK =
        (64 * QSTR + 64 * KSTR + 64 * KSTR + 64 * MXSTR) * (int)sizeof(float); // 93440 B
    cudaFuncSetAttribute(k_topk2, cudaFuncAttributeMaxDynamicSharedMemorySize, SMEM_TOPK);

    // fork/join resources: created per call (2 calls total: correctness + capture);
    // not device memory, intentionally not destroyed mid-capture.
    cudaStream_t s2;
    cudaStreamCreateWithFlags(&s2, cudaStreamNonBlocking);
    cudaEvent_t e1, e2;
    cudaEventCreateWithFlags(&e1, cudaEventDisableTiming);
    cudaEventCreateWithFlags(&e2, cudaEventDisableTiming);

    // ---- serial prologue: rna graph ----
    k_zero<<<1, 32>>>();                                 // launch 1
    k_norm<<<NPTS / 4, 128>>>(zr, za);                   // launch 2
    k_nop<<<1, 32>>>();                                  // launch 3 (profiler shim)
    k_topk2<<<dim3(64, 1, 2), 256, SMEM_TOPK>>>(0);      // launch 4 — rna, profiled
    k_topk_merge<<<16, 256>>>(0);                        // rna graph ready

    // ---- fork: atac graph on s2, rna-dependent chain on main ----
    cudaEventRecord(e1, 0);
    cudaStreamWaitEvent(s2, e1, 0);
    k_topk2<<<dim3(64, 1, 2), 256, SMEM_TOPK, s2>>>(1);  // atac topk (compute-bound)
    k_topk_merge<<<16, 256, 0, s2>>>(1);
    cudaEventRecord(e2, s2);

    k_negs<<<NPTS, 256>>>(noise);                        // DRAM-bound (rna graph only)
    k_ppr_first<<<NPTS, 256>>>();                        // L2-bound (rna graph only)
    for (int it = 0; it < 3; it++)
        k_ppr_iter<<<NPTS, 256>>>(it);                   // X4 -> g_T8

    // ---- join: atac graph required below ----
    cudaStreamWaitEvent(0, e2, 0);
    k_ppr_last<<<NPTS, 256>>>();                         // X5 stats fused (needs atac)
    k_pair<<<NPTS / 8, 256>>>();                         // needs both graphs + negs
    k_final<<<1, 1>>>(out);
}

// round 15
// speedup vs baseline: 1.1715x; 1.0035x over previous
#include <cuda_runtime.h>
#include <cuda_fp16.h>
#include <cuda_fp8.h>
#include <math.h>
#include <stdint.h>

#define NPTS 4096
#define DIM  64
#define KNN  15
#define NNEG 32
#define TEMP_INV 10.0f
#define MARGIN 0.5f
#define FULLMASK 0xffffffffu
#define NEG_THRESH 0.98f
#define PPR_SCALE 64.0f

// ---------------- device scratch (allocation-free per rules) ----------------
__device__ float g_zr[NPTS * DIM];        // normalized z_rna
__device__ float g_za[NPTS * DIM];        // normalized z_atac
__device__ float g_anorm[NPTS];           // raw ||z_atac_i||
__device__ int   g_ir[NPTS * KNN];        // rna knn indices
__device__ float g_wr[NPTS * KNN];        // rna softmax weights
__device__ int   g_ia[NPTS * KNN];        // atac knn indices
__device__ float g_wa[NPTS * KNN];        // atac softmax weights
__device__ int   g_ineg[NPTS * NNEG];     // negative sample indices
__device__ float g_cv2[2 * NPTS * 4 * 16];   // topk quarter-candidates (values, sorted desc)
__device__ int   g_ci2[2 * NPTS * 4 * 16];   // topk quarter-candidates (indices)
__device__ unsigned char g_S8[(size_t)NPTS * NPTS];  // 16MB ping (fp8 e4m3, stores 64*S)
__device__ unsigned char g_T8[(size_t)NPTS * NPTS];  // 16MB pong
__device__ double g_acc[8];               // 0:align 1:attr 2:rep 3:lap_cross 4:fro 5:diff

// ---------------- zero accumulators / nop (launch-order shim for profiling) ----------------
__global__ void k_zero() {
    if (threadIdx.x < 8) g_acc[threadIdx.x] = 0.0;
}
__global__ void k_nop() {}

// ---------------- normalize rows, collect raw atac norms + Frobenius ----------------
__global__ __launch_bounds__(128) void k_norm(const float* __restrict__ zr,
                                              const float* __restrict__ za) {
    int warp = threadIdx.x >> 5, lane = threadIdx.x & 31;
    int r = blockIdx.x * 4 + warp;
    float a0 = zr[r * DIM + lane],      a1 = zr[r * DIM + 32 + lane];
    float b0 = za[r * DIM + lane],      b1 = za[r * DIM + 32 + lane];
    float sr = a0 * a0 + a1 * a1;
    float sa = b0 * b0 + b1 * b1;
    #pragma unroll
    for (int o = 16; o; o >>= 1) {
        sr += __shfl_xor_sync(FULLMASK, sr, o);
        sa += __shfl_xor_sync(FULLMASK, sa, o);
    }
    float nr = fmaxf(sqrtf(sr), 1e-12f);
    float na = fmaxf(sqrtf(sa), 1e-12f);
    g_zr[r * DIM + lane]      = a0 / nr;
    g_zr[r * DIM + 32 + lane] = a1 / nr;
    g_za[r * DIM + lane]      = b0 / na;
    g_za[r * DIM + 32 + lane] = b1 / na;
    if (lane == 0) {
        g_anorm[r] = na;
        atomicAdd(&g_acc[4], (double)sa);   // Frobenius^2 of raw z_atac
    }
}

// ---------------- packed f32x2 helpers ----------------
__device__ __forceinline__ unsigned long long pack2(float x) {
    unsigned long long r;
    asm("mov.b64 %0, {%1, %1};" : "=l"(r) : "f"(x));
    return r;
}
__device__ __forceinline__ unsigned long long fma2(unsigned long long a,
                                                   unsigned long long b,
                                                   unsigned long long c) {
    unsigned long long d;
    asm("fma.rn.f32x2 %0, %1, %2, %3;" : "=l"(d) : "l"(a), "l"(b), "l"(c));
    return d;
}
__device__ __forceinline__ void unpack2(unsigned long long p, float& lo, float& hi) {
    asm("mov.b64 {%0, %1}, %2;" : "=f"(lo), "=f"(hi) : "l"(p));
}

// ---------------- register-tiled sim GEMM (f32x2, R12 geometry) + per-quarter top-15 ----------------
// grid (64, 1, 4): x = query tile (64 q), z = key quarter (1024 keys). `which` selects graph.
#define QSTR 68    // Qt row stride in floats (17 granules)
#define KSTR 132   // Kt/Sc row stride in floats (33 granules)
#define MXSTR 33   // Mx row stride in floats

#define INS(vv, jj) do { \
    if ((jj) != q_self && (vv) > vmin) { \
        tv[pmin] = (vv); ti[pmin] = (jj); \
        vmin = tv[0]; pmin = 0; \
        _Pragma("unroll") \
        for (int u = 1; u < KNN; u++) \
            if (tv[u] < vmin) { vmin = tv[u]; pmin = u; } \
    } \
} while (0)

#define FMA2_ROW(ii, aa) \
    acc2[ii][0] = fma2(aa, b0.x, acc2[ii][0]); \
    acc2[ii][1] = fma2(aa, b0.y, acc2[ii][1]); \
    acc2[ii][2] = fma2(aa, b1.x, acc2[ii][2]); \
    acc2[ii][3] = fma2(aa, b1.y, acc2[ii][3]);

__global__ __launch_bounds__(256, 2) void k_topk2(int which) {
    extern __shared__ __align__(16) float smem[];
    float* Qt = smem;                        // 64 * 68  = 4352 floats
    float* Kt = smem + 64 * QSTR;            // 64 * 132 = 8448 floats
    float* Sc = Kt + 64 * KSTR;              // 64 * 132 = 8448 floats
    float* Mx = Sc + 64 * KSTR;              // 64 * 33  = 2112 floats (group maxes)
    float4* Qt4 = (float4*)Qt;
    float4* Kt4 = (float4*)Kt;
    float4* Sc4 = (float4*)Sc;

    int bz = blockIdx.z;
    const float* __restrict__ Zn = which ? g_za : g_zr;
    const float4* Zn4 = (const float4*)Zn;

    int tid = threadIdx.x;
    int tx = tid & 15, ty = tid >> 4;
    int qbase = blockIdx.x * 64;
    int q_loc = tid >> 2, part = tid & 3;
    int q_self = qbase + q_loc;

    // ---- load + transpose Q tile (64 q x 64 d), dim-major swizzled ----
    #pragma unroll
    for (int l = 0; l < 4; l++) {
        int idx = tid + l * 256;
        int q = idx >> 4, d4 = idx & 15;
        float4 v = Zn4[(qbase + q) * 16 + d4];
        int qg = q >> 2, qr = q & 3;
        int sw = d4 & 7;
        int base = ((qg ^ sw) << 2) + qr;
        Qt[(4 * d4 + 0) * QSTR + base] = v.x;
        Qt[(4 * d4 + 1) * QSTR + base] = v.y;
        Qt[(4 * d4 + 2) * QSTR + base] = v.z;
        Qt[(4 * d4 + 3) * QSTR + base] = v.w;
    }

    float tv[KNN]; int ti[KNN];
    #pragma unroll
    for (int u = 0; u < KNN; u++) { tv[u] = -1e30f; ti[u] = 0; }
    float vmin = -1e30f; int pmin = 0;

    int kend = bz * 8 + 8;
    for (int kt = bz * 8; kt < kend; kt++) {
        int kbase = kt * 128;
        __syncthreads();   // prev GEMM reads of Kt done; safe to overwrite
        // ---- load + transpose K tile (128 k x 64 d), dim-major swizzled ----
        #pragma unroll
        for (int l = 0; l < 8; l++) {
            int idx = tid + l * 256;
            int k = idx >> 4, d4 = idx & 15;
            float4 v = Zn4[(kbase + k) * 16 + d4];
            int kg = k >> 2, kr = k & 3;
            int sw = d4 & 7;
            int base = ((kg ^ sw) << 2) + kr;
            Kt[(4 * d4 + 0) * KSTR + base] = v.x;
            Kt[(4 * d4 + 1) * KSTR + base] = v.y;
            Kt[(4 * d4 + 2) * KSTR + base] = v.z;
            Kt[(4 * d4 + 3) * KSTR + base] = v.w;
        }
        __syncthreads();

        // ---- compute 4x8 register tile as 4x4 f32x2 pairs ----
        unsigned long long acc2[4][4];
        #pragma unroll
        for (int i = 0; i < 4; i++)
            #pragma unroll
            for (int j = 0; j < 4; j++) acc2[i][j] = 0ull;

        #pragma unroll
        for (int d4 = 0; d4 < 16; d4++) {
            int w = d4 & 7;
            const float4*     qp = Qt4 + d4 * 68 + (ty ^ w);                    // 4*d4*17
            const ulonglong2* kp = (const ulonglong2*)(Kt4 + d4 * 132 + (tx ^ w)); // 4*d4*33
            #pragma unroll
            for (int e = 0; e < 4; e++) {
                float4 a      = qp[e * 17];   // 4 queries, dim 4*d4+e
                ulonglong2 b0 = kp[e * 33];        // keys 4tx..4tx+3 (2 pairs)
                ulonglong2 b1 = kp[e * 33 + 16];   // keys 64+4tx..   (2 pairs)
                unsigned long long a0 = pack2(a.x);
                unsigned long long a1 = pack2(a.y);
                unsigned long long a2 = pack2(a.z);
                unsigned long long a3 = pack2(a.w);
                FMA2_ROW(0, a0)
                FMA2_ROW(1, a1)
                FMA2_ROW(2, a2)
                FMA2_ROW(3, a3)
            }
        }

        // ---- write score tile (bit-copy of pairs) + per-4-key group maxes ----
        #pragma unroll
        for (int i = 0; i < 4; i++) {
            ulonglong2 s0; s0.x = acc2[i][0]; s0.y = acc2[i][1];
            ulonglong2 s1; s1.x = acc2[i][2]; s1.y = acc2[i][3];
            *(ulonglong2*)&Sc4[(ty * 4 + i) * 33 + tx]      = s0;
            *(ulonglong2*)&Sc4[(ty * 4 + i) * 33 + 16 + tx] = s1;
            float l0, h0, l1, h1, l2, h2, l3, h3;
            unpack2(acc2[i][0], l0, h0); unpack2(acc2[i][1], l1, h1);
            unpack2(acc2[i][2], l2, h2); unpack2(acc2[i][3], l3, h3);
            Mx[(ty * 4 + i) * MXSTR + tx]      = fmaxf(fmaxf(l0, h0), fmaxf(l1, h1));
            Mx[(ty * 4 + i) * MXSTR + 16 + tx] = fmaxf(fmaxf(l2, h2), fmaxf(l3, h3));
        }
        __syncthreads();

        // ---- insert: 4 threads/query, 8 key-groups each; scan group only if max beats vmin ----
        int gb = part * 8;
        #pragma unroll
        for (int g8 = 0; g8 < 8; g8++) {
            int g = gb + g8;
            float gmax = Mx[q_loc * MXSTR + g];
            if (gmax > vmin) {
                float4 s = Sc4[q_loc * 33 + g];
                int jg = kbase + 4 * g;
                INS(s.x, jg);
                INS(s.y, jg + 1);
                INS(s.z, jg + 2);
                INS(s.w, jg + 3);
            }
        }
    }
    __syncthreads();

    // ---- merge 4 per-part lists (60 candidates/query), emit quarter top-15 sorted desc ----
    float* candv = smem;                      // overlays Qt
    int*   candi = (int*)(smem + 64 * QSTR);  // overlays Kt
    int cb = q_loc * 60 + part * KNN;
    #pragma unroll
    for (int u = 0; u < KNN; u++) { candv[cb + u] = tv[u]; candi[cb + u] = ti[u]; }
    __syncthreads();

    if (tid < 64) {
        int b = tid * 60;
        int qq = qbase + tid;
        size_t ob = ((size_t)(which * NPTS + qq) * 4 + bz) * 16;
        for (int s = 0; s < KNN; s++) {
            float bv = -2e30f; int bp = 0;
            for (int c = 0; c < 60; c++) {
                float v = candv[b + c];
                if (v > bv) { bv = v; bp = c; }
            }
            g_cv2[ob + s] = bv;
            g_ci2[ob + s] = candi[b + bp];
            candv[b + bp] = -3e30f;
        }
    }
}

// ---------------- two-pointer merge of two sorted-desc 15-lists, keep top-15 ----------------
__device__ __forceinline__ void merge2(const float* av, const int* ai,
                                       const float* bv, const int* bi,
                                       float* ov, int* oi) {
    int p0 = 0, p1 = 0;
    #pragma unroll
    for (int s = 0; s < KNN; s++) {
        bool take0 = (p1 >= KNN) ||
                     ((p0 < KNN) && ((av[p0] > bv[p1]) ||
                      (av[p0] == bv[p1] && ai[p0] < bi[p1])));
        if (take0) { ov[s] = av[p0]; oi[s] = ai[p0]; p0++; }
        else       { ov[s] = bv[p1]; oi[s] = bi[p1]; p1++; }
    }
}

// ---------------- merge 4 key-quarters (tournament of merge2), softmax, write ----------------
__global__ __launch_bounds__(256) void k_topk_merge(int which) {
    int q = blockIdx.x * 256 + threadIdx.x;   // 0..4095
    int*   __restrict__ oi = which ? g_ia : g_ir;
    float* __restrict__ ow = which ? g_wa : g_wr;
    size_t cb = (size_t)(which * NPTS + q) * 64;
    float l0v[KNN], l1v[KNN], l2v[KNN], l3v[KNN];
    int   l0i[KNN], l1i[KNN], l2i[KNN], l3i[KNN];
    #pragma unroll
    for (int s = 0; s < KNN; s++) {
        l0v[s] = g_cv2[cb + s];      l0i[s] = g_ci2[cb + s];
        l1v[s] = g_cv2[cb + 16 + s]; l1i[s] = g_ci2[cb + 16 + s];
        l2v[s] = g_cv2[cb + 32 + s]; l2i[s] = g_ci2[cb + 32 + s];
        l3v[s] = g_cv2[cb + 48 + s]; l3i[s] = g_ci2[cb + 48 + s];
    }
    float m01v[KNN], m23v[KNN], selv[KNN];
    int   m01i[KNN], m23i[KNN], seli[KNN];
    merge2(l0v, l0i, l1v, l1i, m01v, m01i);
    merge2(l2v, l2i, l3v, l3i, m23v, m23i);
    merge2(m01v, m01i, m23v, m23i, selv, seli);

    float m = selv[0], sum = 0.f;
    float wv[KNN];
    #pragma unroll
    for (int s = 0; s < KNN; s++) { wv[s] = expf((selv[s] - m) * TEMP_INV); sum += wv[s]; }
    float inv = 1.f / sum;
    #pragma unroll
    for (int s = 0; s < KNN; s++) {
        oi[q * KNN + s] = seli[s];
        ow[q * KNN + s] = wv[s] * inv;
    }
}

// ---------------- negative sampling: ballot-compacted threshold filter (block per row) ----------------
__global__ __launch_bounds__(256) void k_negs(const float* __restrict__ noise) {
    __shared__ float cv[NPTS];
    __shared__ int   ci[NPTS];
    __shared__ int   s_cnt, s_valid;
    __shared__ int   s_nb[KNN];
    int r = blockIdx.x, tid = threadIdx.x, lane = tid & 31;
    if (tid == 0) { s_cnt = 0; s_valid = 0; }
    if (tid < KNN) s_nb[tid] = g_ir[r * KNN + tid];
    __syncthreads();

    const float4* row4 = (const float4*)(noise + (size_t)r * NPTS);
    float4 v[4];
    #pragma unroll
    for (int k = 0; k < 4; k++) v[k] = row4[tid + 256 * k];

    // phase 1: collect all values > thresh (mask deferred), warp-ballot compaction
    #pragma unroll
    for (int k = 0; k < 4; k++) {
        float vals[4] = {v[k].x, v[k].y, v[k].z, v[k].w};
        #pragma unroll
        for (int e = 0; e < 4; e++) {
            int idx = 4 * (tid + 256 * k) + e;
            bool f = (vals[e] > NEG_THRESH) && (idx != r);
            unsigned bal = __ballot_sync(FULLMASK, f);
            if (bal) {
                int wbase;
                if (lane == 0) wbase = atomicAdd(&s_cnt, __popc(bal));
                wbase = __shfl_sync(FULLMASK, wbase, 0);
                if (f) {
                    int pos = wbase + __popc(bal & ((1u << lane) - 1u));
                    cv[pos] = vals[e]; ci[pos] = idx;
                }
            }
        }
    }
    __syncthreads();
    int cnt = s_cnt;

    // phase 2: mark rna-neighbors invalid, count survivors
    {
        int c = 0;
        for (int i = tid; i < cnt; i += 256) {
            int ii = ci[i];
            bool nb = false;
            #pragma unroll
            for (int t = 0; t < KNN; t++) nb |= (s_nb[t] == ii);
            if (nb) cv[i] = -10.f; else c++;
        }
        #pragma unroll
        for (int o = 16; o; o >>= 1) c += __shfl_xor_sync(FULLMASK, c, o);
        if (lane == 0 && c) atomicAdd(&s_valid, c);
    }
    __syncthreads();

    // fallback (probability ~0): collect every unmasked element
    if (s_valid < NNEG) {
        if (tid == 0) s_cnt = 0;
        __syncthreads();
        #pragma unroll
        for (int k = 0; k < 4; k++) {
            float vals[4] = {v[k].x, v[k].y, v[k].z, v[k].w};
            #pragma unroll
            for (int e = 0; e < 4; e++) {
                int idx = 4 * (tid + 256 * k) + e;
                bool nb = (idx == r);
                #pragma unroll
                for (int t = 0; t < KNN; t++) nb |= (s_nb[t] == idx);
                if (!nb) {
                    int p = atomicAdd(&s_cnt, 1);
                    cv[p] = vals[e]; ci[p] = idx;
                }
            }
        }
        __syncthreads();
        cnt = s_cnt;
    }

    // phase 3: rank select (top_k semantics: value desc, index asc on ties)
    for (int i = tid; i < cnt; i += 256) {
        float vi = cv[i]; int ii = ci[i];
        if (vi <= -5.f) continue;
        int rank = 0;
        for (int j = 0; j < cnt; j++) {
            float vj = cv[j];
            rank += (vj > vi) || (vj == vi && ci[j] < ii);
        }
        if (rank < NNEG) g_ineg[r * NNEG + rank] = ii;
    }
}

// ---------------- align-KL + attraction + repulsion + Laplacian cross (warp per row) ----------------
__global__ __launch_bounds__(256) void k_pair() {
    int warp = threadIdx.x >> 5, lane = threadIdx.x & 31;
    int r = blockIdx.x * 8 + warp;
    float q0 = g_za[r * DIM + lane], q1 = g_za[r * DIM + 32 + lane];
    int   irv = (lane < KNN) ? g_ir[r * KNN + lane] : 0;
    float wrv = (lane < KNN) ? g_wr[r * KNN + lane] : 0.f;
    int   iav = (lane < KNN) ? g_ia[r * KNN + lane] : -1;
    float wav = (lane < KNN) ? g_wa[r * KNN + lane] : 0.f;
    int   negv = g_ineg[r * NNEG + lane];
    float anr = g_anorm[r];
    float align_s = 0.f, attr_s = 0.f, lap_s = 0.f, rep_s = 0.f;

    float x0[KNN], x1[KNN];
    #pragma unroll
    for (int t = 0; t < KNN; t++) {
        int j = __shfl_sync(FULLMASK, irv, t);
        x0[t] = g_za[j * DIM + lane];
        x1[t] = g_za[j * DIM + 32 + lane];
    }
    #pragma unroll
    for (int t = 0; t < KNN; t++) {
        int   j  = __shfl_sync(FULLMASK, irv, t);
        float tw = __shfl_sync(FULLMASK, wrv, t);
        float d = q0 * x0[t] + q1 * x1[t];
        #pragma unroll
        for (int o = 16; o; o >>= 1) d += __shfl_xor_sync(FULLMASK, d, o);
        unsigned bl = __ballot_sync(FULLMASK, (lane < KNN) && (iav == j));
        float aeq = 0.f;
        if (bl) aeq = __shfl_sync(FULLMASK, wav, __ffs(bl) - 1);
        float anj = g_anorm[j];
        if (lane == 0) {
            attr_s  += 1.f - d;
            lap_s   += anr * anj * d;
            align_s += tw * (logf(tw) - logf(aeq + 1e-8f));
        }
    }
    #pragma unroll
    for (int m8 = 0; m8 < 4; m8++) {
        float y0[8], y1[8];
        #pragma unroll
        for (int u = 0; u < 8; u++) {
            int j = __shfl_sync(FULLMASK, negv, m8 * 8 + u);
            y0[u] = g_za[j * DIM + lane];
            y1[u] = g_za[j * DIM + 32 + lane];
        }
        #pragma unroll
        for (int u = 0; u < 8; u++) {
            float d = q0 * y0[u] + q1 * y1[u];
            #pragma unroll
            for (int o = 16; o; o >>= 1) d += __shfl_xor_sync(FULLMASK, d, o);
            if (lane == 0) rep_s += fmaxf(MARGIN - (1.f - d), 0.f);
        }
    }
    if (lane == 0) {
        atomicAdd(&g_acc[0], (double)align_s);
        atomicAdd(&g_acc[1], (double)(attr_s / (float)KNN));
        atomicAdd(&g_acc[2], (double)rep_s);
        atomicAdd(&g_acc[3], (double)lap_s);
    }
}

// ---------------- PPR step 1 sparse-sparse: X1 = 64*(0.8*A@A + 0.2*A) -> g_S8 (fp8) ----------------
__global__ __launch_bounds__(256) void k_ppr_first() {
    __shared__ float srow[NPTS];
    __shared__ int sj[KNN]; __shared__ float sw_[KNN];
    int r = blockIdx.x, tid = threadIdx.x;
    if (tid < KNN) { sj[tid] = g_ir[r * KNN + tid]; sw_[tid] = g_wr[r * KNN + tid]; }
    float4* sr4 = (float4*)srow;
    float4 z = {0.f, 0.f, 0.f, 0.f};
    #pragma unroll
    for (int k = 0; k < 4; k++) sr4[tid + 256 * k] = z;
    __syncthreads();
    if (tid < KNN * KNN) {
        int t = tid / KNN, u = tid % KNN;
        int j = sj[t];
        atomicAdd(&srow[g_ir[j * KNN + u]], 0.8f * sw_[t] * g_wr[j * KNN + u]);
    }
    if (tid < KNN) atomicAdd(&srow[sj[tid]], 0.2f * sw_[tid]);
    __syncthreads();
    uint4 ov;
    __nv_fp8x2_storage_t* po = (__nv_fp8x2_storage_t*)&ov;
    #pragma unroll
    for (int e = 0; e < 8; e++) {
        float2 f;
        f.x = PPR_SCALE * srow[16 * tid + 2 * e];
        f.y = PPR_SCALE * srow[16 * tid + 2 * e + 1];
        po[e] = __nv_cvt_float2_to_fp8x2(f, __NV_SATFINITE, __NV_E4M3);
    }
    ((uint4*)(g_S8 + (size_t)r * NPTS))[tid] = ov;
}

// ---------------- dense PPR iteration (fp8 S, half2 accumulate): X' = 0.8*A@X + 12.8*A ----------------
__global__ __launch_bounds__(256) void k_ppr_iter(int it) {
    const unsigned char* __restrict__ src = (it & 1) ? g_T8 : g_S8;
    unsigned char* __restrict__ dst       = (it & 1) ? g_S8 : g_T8;
    int r = blockIdx.x, tid = threadIdx.x;
    __shared__ int sj[KNN]; __shared__ float sw_[KNN];
    if (tid < KNN) { sj[tid] = g_ir[r * KNN + tid]; sw_[tid] = g_wr[r * KNN + tid]; }
    __syncthreads();
    int rj[KNN]; __half2 rw[KNN];
    #pragma unroll
    for (int t = 0; t < KNN; t++) { rj[t] = sj[t]; rw[t] = __float2half2_rn(sw_[t]); }

    const uint4* s4 = (const uint4*)src;   // 256 uint4 (4096 fp8) per row
    __half2 acc[8];
    #pragma unroll
    for (int e = 0; e < 8; e++) acc[e] = __float2half2_rn(0.f);
    #pragma unroll
    for (int t = 0; t < KNN; t++) {
        uint4 v = s4[(size_t)rj[t] * 256 + tid];
        const __nv_fp8x2_storage_t* pv = (const __nv_fp8x2_storage_t*)&v;
        #pragma unroll
        for (int e = 0; e < 8; e++) {
            __half2_raw hr = __nv_cvt_fp8x2_to_halfraw2(pv[e], __NV_E4M3);
            acc[e] = __hfma2(*(__half2*)&hr, rw[t], acc[e]);
        }
    }
    __half2 c08 = __float2half2_rn(0.8f);
    uint4 ov;
    __nv_fp8x2_storage_t* po = (__nv_fp8x2_storage_t*)&ov;
    #pragma unroll
    for (int e = 0; e < 8; e++) {
        __half2 o = __hmul2(acc[e], c08);
        po[e] = __nv_cvt_halfraw2_to_fp8x2(*(__half2_raw*)&o, __NV_SATFINITE, __NV_E4M3);
    }
    ((uint4*)(dst + (size_t)r * NPTS))[tid] = ov;
    __syncthreads();
    if (tid < KNN) {
        size_t p = (size_t)r * NPTS + sj[tid];
        __half_raw h = __nv_cvt_fp8_to_halfraw(dst[p], __NV_E4M3);
        float val = __half2float(*(__half*)&h) + 0.2f * PPR_SCALE * sw_[tid];
        dst[p] = __nv_cvt_float_to_fp8(val, __NV_SATFINITE, __NV_E4M3);
    }
}

// ---------------- last PPR iteration fused with diff stats (no S5 store) ----------------
__global__ __launch_bounds__(256) void k_ppr_last() {
    __shared__ float srow[NPTS];
    __shared__ float s1[256], s2[256];
    __shared__ int sj[KNN]; __shared__ float sw_[KNN];
    int r = blockIdx.x, tid = threadIdx.x;
    if (tid < KNN) { sj[tid] = g_ir[r * KNN + tid]; sw_[tid] = g_wr[r * KNN + tid]; }
    __syncthreads();
    int rj[KNN]; __half2 rw[KNN];
    #pragma unroll
    for (int t = 0; t < KNN; t++) { rj[t] = sj[t]; rw[t] = __float2half2_rn(sw_[t]); }

    const uint4* s4 = (const uint4*)g_T8;
    __half2 acc[8];
    #pragma unroll
    for (int e = 0; e < 8; e++) acc[e] = __float2half2_rn(0.f);
    #pragma unroll
    for (int t = 0; t < KNN; t++) {
        uint4 v = s4[(size_t)rj[t] * 256 + tid];
        const __nv_fp8x2_storage_t* pv = (const __nv_fp8x2_storage_t*)&v;
        #pragma unroll
        for (int e = 0; e < 8; e++) {
            __half2_raw hr = __nv_cvt_fp8x2_to_halfraw2(pv[e], __NV_E4M3);
            acc[e] = __hfma2(*(__half2*)&hr, rw[t], acc[e]);
        }
    }
    #pragma unroll
    for (int e = 0; e < 8; e++) {
        float2 f = __half22float2(acc[e]);
        srow[16 * tid + 2 * e]     = 0.8f * f.x;
        srow[16 * tid + 2 * e + 1] = 0.8f * f.y;
    }
    __syncthreads();
    if (tid < KNN) atomicAdd(&srow[sj[tid]], 0.2f * PPR_SCALE * sw_[tid]);
    __syncthreads();
    float sum = 0.f, sq = 0.f;
    #pragma unroll
    for (int e = 0; e < 16; e++) {
        float v = srow[16 * tid + e];
        sum += v; sq += v * v;
    }
    s1[tid] = sum; s2[tid] = sq;
    __syncthreads();
    for (int o = 128; o; o >>= 1) {
        if (tid < o) { s1[tid] += s1[tid + o]; s2[tid] += s2[tid + o]; }
        __syncthreads();
    }
    if (tid == 0) {
        float rs = s1[0] * (1.f / PPR_SCALE);
        float rq = s2[0] * (1.f / (PPR_SCALE * PPR_SCALE));
        float rinv = 1.f / fmaxf(rs, 1e-8f);
        float cross = 0.f, a2 = 0.f;
        for (int t = 0; t < KNN; t++) {
            int c = g_ia[r * KNN + t];
            float a = g_wa[r * KNN + t];
            cross += a * srow[c] * (1.f / PPR_SCALE);
            a2 += a * a;
        }
        double rowdiff = (double)rq * rinv * rinv - 2.0 * (double)rinv * (double)cross + (double)a2;
        atomicAdd(&g_acc[5], rowdiff);
    }
}

// ---------------- combine ----------------
__global__ void k_final(float* out) {
    double align = g_acc[0] / 4096.0;
    double attr  = g_acc[1] / 4096.0;
    double rep   = g_acc[2] / (4096.0 * 32.0);
    double lap   = (g_acc[4] - g_acc[3] / 15.0) / 4096.0;
    double diff  = g_acc[5] / (4096.0 * 4096.0);
    out[0] = (float)(align + (attr + rep) + 0.5 * lap + 0.5 * diff);
}

extern "C" void kernel_launch(void* const* d_in, const int* in_sizes, int n_in,
                              void* d_out, int out_size) {
    (void)in_sizes; (void)n_in; (void)out_size;
    const float* zr    = (const float*)d_in[0];
    const float* za    = (const float*)d_in[1];
    const float* noise = (const float*)d_in[2];
    float* out = (float*)d_out;

    const int SMEM_TOPK =
        (64 * QSTR + 64 * KSTR + 64 * KSTR + 64 * MXSTR) * (int)sizeof(float); // 93440 B
    cudaFuncSetAttribute(k_topk2, cudaFuncAttributeMaxDynamicSharedMemorySize, SMEM_TOPK);

    // fork/join resources: host-side handles only (not device memory).
    cudaStream_t s2;
    cudaStreamCreateWithFlags(&s2, cudaStreamNonBlocking);
    cudaEvent_t e1, e2;
    cudaEventCreateWithFlags(&e1, cudaEventDisableTiming);
    cudaEventCreateWithFlags(&e2, cudaEventDisableTiming);

    // ---- serial prologue: rna graph (full-machine grid: 256 blocks) ----
    k_zero<<<1, 32>>>();                                 // launch 1
    k_norm<<<NPTS / 4, 128>>>(zr, za);                   // launch 2
    k_nop<<<1, 32>>>();                                  // launch 3 (profiler shim)
    k_topk2<<<dim3(64, 1, 4), 256, SMEM_TOPK>>>(0);      // launch 4 — rna, profiled
    k_topk_merge<<<16, 256>>>(0);                        // rna graph ready

    // ---- fork: atac graph on s2, rna-dependent chain on main ----
    cudaEventRecord(e1, 0);
    cudaStreamWaitEvent(s2, e1, 0);
    k_topk2<<<dim3(64, 1, 4), 256, SMEM_TOPK, s2>>>(1);  // atac topk (compute-bound)
    k_topk_merge<<<16, 256, 0, s2>>>(1);
    cudaEventRecord(e2, s2);

    k_negs<<<NPTS, 256>>>(noise);                        // DRAM-bound (rna graph only)
    k_ppr_first<<<NPTS, 256>>>();                        // L2-bound (rna graph only)
    for (int it = 0; it < 3; it++)
        k_ppr_iter<<<NPTS, 256>>>(it);                   // X4 -> g_T8

    // ---- join: atac graph required below ----
    cudaStreamWaitEvent(0, e2, 0);
    k_ppr_last<<<NPTS, 256>>>();                         // X5 stats fused (needs atac)
    k_pair<<<NPTS / 8, 256>>>();                         // needs both graphs + negs
    k_final<<<1, 1>>>(out);
}

// round 16
// speedup vs baseline: 1.3201x; 1.1268x over previous
#include <cuda_runtime.h>
#include <cuda_fp16.h>
#include <cuda_fp8.h>
#include <math.h>
#include <stdint.h>

#define NPTS 4096
#define DIM  64
#define KNN  15
#define NNEG 32
#define NCAND 64
#define TEMP_INV 10.0f
#define MARGIN 0.5f
#define FULLMASK 0xffffffffu
#define NEG_THRESH 0.97f
#define PPR_SCALE 64.0f

// ---------------- device scratch (allocation-free per rules) ----------------
__device__ float g_zr[NPTS * DIM];        // normalized z_rna
__device__ float g_za[NPTS * DIM];        // normalized z_atac
__device__ float g_anorm[NPTS];           // raw ||z_atac_i||
__device__ int   g_ir[NPTS * KNN];        // rna knn indices
__device__ float g_wr[NPTS * KNN];        // rna softmax weights
__device__ int   g_ia[NPTS * KNN];        // atac knn indices
__device__ float g_wa[NPTS * KNN];        // atac softmax weights
__device__ int   g_negcand[NPTS * NCAND]; // maskless top-64 noise candidates (rank order)
__device__ int   g_ineg[NPTS * NNEG];     // negative sample indices
__device__ float g_cv2[2 * NPTS * 2 * 16];   // topk half-candidates (values, sorted desc)
__device__ int   g_ci2[2 * NPTS * 2 * 16];   // topk half-candidates (indices)
__device__ unsigned char g_S8[(size_t)NPTS * NPTS];  // 16MB ping (fp8 e4m3, stores 64*S)
__device__ unsigned char g_T8[(size_t)NPTS * NPTS];  // 16MB pong
__device__ double g_acc[8];               // 0:align 1:attr 2:rep 3:lap_cross 4:fro 5:diff

// ---------------- zero accumulators ----------------
__global__ void k_zero() {
    if (threadIdx.x < 8) g_acc[threadIdx.x] = 0.0;
}

// ---------------- normalize rows, collect raw atac norms + Frobenius ----------------
__global__ __launch_bounds__(128) void k_norm(const float* __restrict__ zr,
                                              const float* __restrict__ za) {
    int warp = threadIdx.x >> 5, lane = threadIdx.x & 31;
    int r = blockIdx.x * 4 + warp;
    float a0 = zr[r * DIM + lane],      a1 = zr[r * DIM + 32 + lane];
    float b0 = za[r * DIM + lane],      b1 = za[r * DIM + 32 + lane];
    float sr = a0 * a0 + a1 * a1;
    float sa = b0 * b0 + b1 * b1;
    #pragma unroll
    for (int o = 16; o; o >>= 1) {
        sr += __shfl_xor_sync(FULLMASK, sr, o);
        sa += __shfl_xor_sync(FULLMASK, sa, o);
    }
    float nr = fmaxf(sqrtf(sr), 1e-12f);
    float na = fmaxf(sqrtf(sa), 1e-12f);
    g_zr[r * DIM + lane]      = a0 / nr;
    g_zr[r * DIM + 32 + lane] = a1 / nr;
    g_za[r * DIM + lane]      = b0 / na;
    g_za[r * DIM + 32 + lane] = b1 / na;
    if (lane == 0) {
        g_anorm[r] = na;
        atomicAdd(&g_acc[4], (double)sa);   // Frobenius^2 of raw z_atac
    }
}

// ---------------- packed f32x2 helpers ----------------
__device__ __forceinline__ unsigned long long pack2(float x) {
    unsigned long long r;
    asm("mov.b64 %0, {%1, %1};" : "=l"(r) : "f"(x));
    return r;
}
__device__ __forceinline__ unsigned long long fma2(unsigned long long a,
                                                   unsigned long long b,
                                                   unsigned long long c) {
    unsigned long long d;
    asm("fma.rn.f32x2 %0, %1, %2, %3;" : "=l"(d) : "l"(a), "l"(b), "l"(c));
    return d;
}
__device__ __forceinline__ void unpack2(unsigned long long p, float& lo, float& hi) {
    asm("mov.b64 {%0, %1}, %2;" : "=f"(lo), "=f"(hi) : "l"(p));
}

// ---------------- fused register-tiled sim GEMM (f32x2) + per-half top-15 (R12) ----------------
// grid (64, 2, 2): x = query tile (64 q), y = which graph, z = key half (2048 keys).
#define QSTR 68    // Qt row stride in floats (17 granules)
#define KSTR 132   // Kt/Sc row stride in floats (33 granules)
#define MXSTR 33   // Mx row stride in floats

#define INS(vv, jj) do { \
    if ((jj) != q_self && (vv) > vmin) { \
        tv[pmin] = (vv); ti[pmin] = (jj); \
        vmin = tv[0]; pmin = 0; \
        _Pragma("unroll") \
        for (int u = 1; u < KNN; u++) \
            if (tv[u] < vmin) { vmin = tv[u]; pmin = u; } \
    } \
} while (0)

#define FMA2_ROW(ii, aa) \
    acc2[ii][0] = fma2(aa, b0.x, acc2[ii][0]); \
    acc2[ii][1] = fma2(aa, b0.y, acc2[ii][1]); \
    acc2[ii][2] = fma2(aa, b1.x, acc2[ii][2]); \
    acc2[ii][3] = fma2(aa, b1.y, acc2[ii][3]);

__global__ __launch_bounds__(256, 2) void k_topk2() {
    extern __shared__ __align__(16) float smem[];
    float* Qt = smem;                        // 64 * 68  = 4352 floats
    float* Kt = smem + 64 * QSTR;            // 64 * 132 = 8448 floats
    float* Sc = Kt + 64 * KSTR;              // 64 * 132 = 8448 floats
    float* Mx = Sc + 64 * KSTR;              // 64 * 33  = 2112 floats (group maxes)
    float4* Qt4 = (float4*)Qt;
    float4* Kt4 = (float4*)Kt;
    float4* Sc4 = (float4*)Sc;

    int which = blockIdx.y;
    int bz = blockIdx.z;
    const float* __restrict__ Zn = which ? g_za : g_zr;
    const float4* Zn4 = (const float4*)Zn;

    int tid = threadIdx.x;
    int tx = tid & 15, ty = tid >> 4;
    int qbase = blockIdx.x * 64;
    int q_loc = tid >> 2, part = tid & 3;
    int q_self = qbase + q_loc;

    // ---- load + transpose Q tile (64 q x 64 d), dim-major swizzled ----
    #pragma unroll
    for (int l = 0; l < 4; l++) {
        int idx = tid + l * 256;
        int q = idx >> 4, d4 = idx & 15;
        float4 v = Zn4[(qbase + q) * 16 + d4];
        int qg = q >> 2, qr = q & 3;
        int sw = d4 & 7;
        int base = ((qg ^ sw) << 2) + qr;
        Qt[(4 * d4 + 0) * QSTR + base] = v.x;
        Qt[(4 * d4 + 1) * QSTR + base] = v.y;
        Qt[(4 * d4 + 2) * QSTR + base] = v.z;
        Qt[(4 * d4 + 3) * QSTR + base] = v.w;
    }

    float tv[KNN]; int ti[KNN];
    #pragma unroll
    for (int u = 0; u < KNN; u++) { tv[u] = -1e30f; ti[u] = 0; }
    float vmin = -1e30f; int pmin = 0;

    int kend = bz * 16 + 16;
    for (int kt = bz * 16; kt < kend; kt++) {
        int kbase = kt * 128;
        __syncthreads();   // prev GEMM reads of Kt done; safe to overwrite
        // ---- load + transpose K tile (128 k x 64 d), dim-major swizzled ----
        #pragma unroll
        for (int l = 0; l < 8; l++) {
            int idx = tid + l * 256;
            int k = idx >> 4, d4 = idx & 15;
            float4 v = Zn4[(kbase + k) * 16 + d4];
            int kg = k >> 2, kr = k & 3;
            int sw = d4 & 7;
            int base = ((kg ^ sw) << 2) + kr;
            Kt[(4 * d4 + 0) * KSTR + base] = v.x;
            Kt[(4 * d4 + 1) * KSTR + base] = v.y;
            Kt[(4 * d4 + 2) * KSTR + base] = v.z;
            Kt[(4 * d4 + 3) * KSTR + base] = v.w;
        }
        __syncthreads();

        // ---- compute 4x8 register tile as 4x4 f32x2 pairs ----
        unsigned long long acc2[4][4];
        #pragma unroll
        for (int i = 0; i < 4; i++)
            #pragma unroll
            for (int j = 0; j < 4; j++) acc2[i][j] = 0ull;

        #pragma unroll
        for (int d4 = 0; d4 < 16; d4++) {
            int w = d4 & 7;
            const float4*     qp = Qt4 + d4 * 68 + (ty ^ w);                    // 4*d4*17
            const ulonglong2* kp = (const ulonglong2*)(Kt4 + d4 * 132 + (tx ^ w)); // 4*d4*33
            #pragma unroll
            for (int e = 0; e < 4; e++) {
                float4 a      = qp[e * 17];   // 4 queries, dim 4*d4+e
                ulonglong2 b0 = kp[e * 33];        // keys 4tx..4tx+3 (2 pairs)
                ulonglong2 b1 = kp[e * 33 + 16];   // keys 64+4tx..   (2 pairs)
                unsigned long long a0 = pack2(a.x);
                unsigned long long a1 = pack2(a.y);
                unsigned long long a2 = pack2(a.z);
                unsigned long long a3 = pack2(a.w);
                FMA2_ROW(0, a0)
                FMA2_ROW(1, a1)
                FMA2_ROW(2, a2)
                FMA2_ROW(3, a3)
            }
        }

        // ---- write score tile (bit-copy of pairs) + per-4-key group maxes ----
        #pragma unroll
        for (int i = 0; i < 4; i++) {
            ulonglong2 s0; s0.x = acc2[i][0]; s0.y = acc2[i][1];
            ulonglong2 s1; s1.x = acc2[i][2]; s1.y = acc2[i][3];
            *(ulonglong2*)&Sc4[(ty * 4 + i) * 33 + tx]      = s0;
            *(ulonglong2*)&Sc4[(ty * 4 + i) * 33 + 16 + tx] = s1;
            float l0, h0, l1, h1, l2, h2, l3, h3;
            unpack2(acc2[i][0], l0, h0); unpack2(acc2[i][1], l1, h1);
            unpack2(acc2[i][2], l2, h2); unpack2(acc2[i][3], l3, h3);
            Mx[(ty * 4 + i) * MXSTR + tx]      = fmaxf(fmaxf(l0, h0), fmaxf(l1, h1));
            Mx[(ty * 4 + i) * MXSTR + 16 + tx] = fmaxf(fmaxf(l2, h2), fmaxf(l3, h3));
        }
        __syncthreads();

        // ---- insert: 4 threads/query, 8 key-groups each; scan group only if max beats vmin ----
        int gb = part * 8;
        #pragma unroll
        for (int g8 = 0; g8 < 8; g8++) {
            int g = gb + g8;
            float gmax = Mx[q_loc * MXSTR + g];
            if (gmax > vmin) {
                float4 s = Sc4[q_loc * 33 + g];
                int jg = kbase + 4 * g;
                INS(s.x, jg);
                INS(s.y, jg + 1);
                INS(s.z, jg + 2);
                INS(s.w, jg + 3);
            }
        }
    }
    __syncthreads();

    // ---- merge 4 per-part lists (60 candidates/query), emit half top-15 sorted desc ----
    float* candv = smem;                      // overlays Qt
    int*   candi = (int*)(smem + 64 * QSTR);  // overlays Kt
    int cb = q_loc * 60 + part * KNN;
    #pragma unroll
    for (int u = 0; u < KNN; u++) { candv[cb + u] = tv[u]; candi[cb + u] = ti[u]; }
    __syncthreads();

    if (tid < 64) {
        int b = tid * 60;
        int qq = qbase + tid;
        size_t ob = ((size_t)(which * NPTS + qq) * 2 + bz) * 16;
        for (int s = 0; s < KNN; s++) {
            float bv = -2e30f; int bp = 0;
            for (int c = 0; c < 60; c++) {
                float v = candv[b + c];
                if (v > bv) { bv = v; bp = c; }
            }
            g_cv2[ob + s] = bv;
            g_ci2[ob + s] = candi[b + bp];
            candv[b + bp] = -3e30f;
        }
    }
}

// ---------------- merge key-halves (two-pointer over sorted lists), softmax, write ----------------
__global__ __launch_bounds__(256) void k_topk_merge() {
    int g = blockIdx.x * 256 + threadIdx.x;   // 0..8191
    int which = g >> 12, q = g & (NPTS - 1);
    int*   __restrict__ oi = which ? g_ia : g_ir;
    float* __restrict__ ow = which ? g_wa : g_wr;
    size_t cb = (size_t)(which * NPTS + q) * 32;
    float av[KNN], bv[KNN]; int ai[KNN], bi[KNN];
    #pragma unroll
    for (int s = 0; s < KNN; s++) {
        av[s] = g_cv2[cb + s];      ai[s] = g_ci2[cb + s];
        bv[s] = g_cv2[cb + 16 + s]; bi[s] = g_ci2[cb + 16 + s];
    }
    int p0 = 0, p1 = 0;
    float selv[KNN]; int seli[KNN];
    #pragma unroll
    for (int s = 0; s < KNN; s++) {
        bool take0 = (p1 >= KNN) ||
                     ((p0 < KNN) && ((av[p0] > bv[p1]) ||
                      (av[p0] == bv[p1] && ai[p0] < bi[p1])));
        if (take0) { selv[s] = av[p0]; seli[s] = ai[p0]; p0++; }
        else       { selv[s] = bv[p1]; seli[s] = bi[p1]; p1++; }
    }
    float m = selv[0], sum = 0.f;
    float wv[KNN];
    #pragma unroll
    for (int s = 0; s < KNN; s++) { wv[s] = expf((selv[s] - m) * TEMP_INV); sum += wv[s]; }
    float inv = 1.f / sum;
    #pragma unroll
    for (int s = 0; s < KNN; s++) {
        oi[q * KNN + s] = seli[s];
        ow[q * KNN + s] = wv[s] * inv;
    }
}

// ---------------- negatives pre-pass: maskless top-64 noise candidates (block per row) ----------------
// Only needs `noise` (+ diag exclusion) -> runs concurrent with k_topk2.
// Threshold 0.97 collects ~123 candidates (P(<64) ~ 3e-8/row); exact fallback rescans all.
__global__ __launch_bounds__(256) void k_negs_pre(const float* __restrict__ noise) {
    __shared__ float cv[NPTS];
    __shared__ int   ci[NPTS];
    __shared__ int   s_cnt;
    int r = blockIdx.x, tid = threadIdx.x, lane = tid & 31;
    if (tid == 0) s_cnt = 0;
    __syncthreads();

    const float4* row4 = (const float4*)(noise + (size_t)r * NPTS);
    float4 v[4];
    #pragma unroll
    for (int k = 0; k < 4; k++) v[k] = row4[tid + 256 * k];

    // phase 1: collect all values > thresh (diag excluded), warp-ballot compaction
    #pragma unroll
    for (int k = 0; k < 4; k++) {
        float vals[4] = {v[k].x, v[k].y, v[k].z, v[k].w};
        #pragma unroll
        for (int e = 0; e < 4; e++) {
            int idx = 4 * (tid + 256 * k) + e;
            bool f = (vals[e] > NEG_THRESH) && (idx != r);
            unsigned bal = __ballot_sync(FULLMASK, f);
            if (bal) {
                int wbase;
                if (lane == 0) wbase = atomicAdd(&s_cnt, __popc(bal));
                wbase = __shfl_sync(FULLMASK, wbase, 0);
                if (f) {
                    int pos = wbase + __popc(bal & ((1u << lane) - 1u));
                    cv[pos] = vals[e]; ci[pos] = idx;
                }
            }
        }
    }
    __syncthreads();
    int cnt = s_cnt;

    // fallback (probability ~0): collect every non-diagonal element
    if (cnt < NCAND) {
        if (tid == 0) s_cnt = 0;
        __syncthreads();
        #pragma unroll
        for (int k = 0; k < 4; k++) {
            float vals[4] = {v[k].x, v[k].y, v[k].z, v[k].w};
            #pragma unroll
            for (int e = 0; e < 4; e++) {
                int idx = 4 * (tid + 256 * k) + e;
                if (idx != r) {
                    int p = atomicAdd(&s_cnt, 1);
                    cv[p] = vals[e]; ci[p] = idx;
                }
            }
        }
        __syncthreads();
        cnt = s_cnt;
    }

    // rank select top-64 (value desc, index asc on ties) -> g_negcand in rank order
    for (int i = tid; i < cnt; i += 256) {
        float vi = cv[i]; int ii = ci[i];
        int rank = 0;
        for (int j = 0; j < cnt; j++) {
            float vj = cv[j];
            rank += (vj > vi) || (vj == vi && ci[j] < ii);
        }
        if (rank < NCAND) g_negcand[r * NCAND + rank] = ii;
    }
}

// ---------------- negatives post-pass: drop rna-neighbors, keep first 32 survivors ----------------
// Exact: <=15 masked items removed from rank-ordered top-64 => top-32 of masked set preserved.
__global__ __launch_bounds__(256) void k_negs_post() {
    int warp = threadIdx.x >> 5, lane = threadIdx.x & 31;
    int r = blockIdx.x * 8 + warp;
    int nbv = (lane < KNN) ? g_ir[r * KNN + lane] : -1;
    int c0 = g_negcand[r * NCAND + lane];
    int c1 = g_negcand[r * NCAND + 32 + lane];
    bool m0 = false, m1 = false;
    #pragma unroll
    for (int t = 0; t < KNN; t++) {
        int nb = __shfl_sync(FULLMASK, nbv, t);
        m0 |= (c0 == nb);
        m1 |= (c1 == nb);
    }
    unsigned b0 = __ballot_sync(FULLMASK, !m0);
    unsigned b1 = __ballot_sync(FULLMASK, !m1);
    int pos0 = __popc(b0 & ((1u << lane) - 1u));
    if (!m0 && pos0 < NNEG) g_ineg[r * NNEG + pos0] = c0;
    int base = __popc(b0);
    int pos1 = base + __popc(b1 & ((1u << lane) - 1u));
    if (!m1 && pos1 < NNEG) g_ineg[r * NNEG + pos1] = c1;
}

// ---------------- align-KL + attraction + repulsion + Laplacian cross (warp per row) ----------------
__global__ __launch_bounds__(256) void k_pair() {
    int warp = threadIdx.x >> 5, lane = threadIdx.x & 31;
    int r = blockIdx.x * 8 + warp;
    float q0 = g_za[r * DIM + lane], q1 = g_za[r * DIM + 32 + lane];
    int   irv = (lane < KNN) ? g_ir[r * KNN + lane] : 0;
    float wrv = (lane < KNN) ? g_wr[r * KNN + lane] : 0.f;
    int   iav = (lane < KNN) ? g_ia[r * KNN + lane] : -1;
    float wav = (lane < KNN) ? g_wa[r * KNN + lane] : 0.f;
    int   negv = g_ineg[r * NNEG + lane];
    float anr = g_anorm[r];
    float align_s = 0.f, attr_s = 0.f, lap_s = 0.f, rep_s = 0.f;

    float x0[KNN], x1[KNN];
    #pragma unroll
    for (int t = 0; t < KNN; t++) {
        int j = __shfl_sync(FULLMASK, irv, t);
        x0[t] = g_za[j * DIM + lane];
        x1[t] = g_za[j * DIM + 32 + lane];
    }
    #pragma unroll
    for (int t = 0; t < KNN; t++) {
        int   j  = __shfl_sync(FULLMASK, irv, t);
        float tw = __shfl_sync(FULLMASK, wrv, t);
        float d = q0 * x0[t] + q1 * x1[t];
        #pragma unroll
        for (int o = 16; o; o >>= 1) d += __shfl_xor_sync(FULLMASK, d, o);
        unsigned bl = __ballot_sync(FULLMASK, (lane < KNN) && (iav == j));
        float aeq = 0.f;
        if (bl) aeq = __shfl_sync(FULLMASK, wav, __ffs(bl) - 1);
        float anj = g_anorm[j];
        if (lane == 0) {
            attr_s  += 1.f - d;
            lap_s   += anr * anj * d;
            align_s += tw * (logf(tw) - logf(aeq + 1e-8f));
        }
    }
    #pragma unroll
    for (int m8 = 0; m8 < 4; m8++) {
        float y0[8], y1[8];
        #pragma unroll
        for (int u = 0; u < 8; u++) {
            int j = __shfl_sync(FULLMASK, negv, m8 * 8 + u);
            y0[u] = g_za[j * DIM + lane];
            y1[u] = g_za[j * DIM + 32 + lane];
        }
        #pragma unroll
        for (int u = 0; u < 8; u++) {
            float d = q0 * y0[u] + q1 * y1[u];
            #pragma unroll
            for (int o = 16; o; o >>= 1) d += __shfl_xor_sync(FULLMASK, d, o);
            if (lane == 0) rep_s += fmaxf(MARGIN - (1.f - d), 0.f);
        }
    }
    if (lane == 0) {
        atomicAdd(&g_acc[0], (double)align_s);
        atomicAdd(&g_acc[1], (double)(attr_s / (float)KNN));
        atomicAdd(&g_acc[2], (double)rep_s);
        atomicAdd(&g_acc[3], (double)lap_s);
    }
}

// ---------------- PPR step 1 sparse-sparse: X1 = 64*(0.8*A@A + 0.2*A) -> g_S8 (fp8) ----------------
__global__ __launch_bounds__(256) void k_ppr_first() {
    __shared__ float srow[NPTS];
    __shared__ int sj[KNN]; __shared__ float sw_[KNN];
    int r = blockIdx.x, tid = threadIdx.x;
    if (tid < KNN) { sj[tid] = g_ir[r * KNN + tid]; sw_[tid] = g_wr[r * KNN + tid]; }
    float4* sr4 = (float4*)srow;
    float4 z = {0.f, 0.f, 0.f, 0.f};
    #pragma unroll
    for (int k = 0; k < 4; k++) sr4[tid + 256 * k] = z;
    __syncthreads();
    if (tid < KNN * KNN) {
        int t = tid / KNN, u = tid % KNN;
        int j = sj[t];
        atomicAdd(&srow[g_ir[j * KNN + u]], 0.8f * sw_[t] * g_wr[j * KNN + u]);
    }
    if (tid < KNN) atomicAdd(&srow[sj[tid]], 0.2f * sw_[tid]);
    __syncthreads();
    uint4 ov;
    __nv_fp8x2_storage_t* po = (__nv_fp8x2_storage_t*)&ov;
    #pragma unroll
    for (int e = 0; e < 8; e++) {
        float2 f;
        f.x = PPR_SCALE * srow[16 * tid + 2 * e];
        f.y = PPR_SCALE * srow[16 * tid + 2 * e + 1];
        po[e] = __nv_cvt_float2_to_fp8x2(f, __NV_SATFINITE, __NV_E4M3);
    }
    ((uint4*)(g_S8 + (size_t)r * NPTS))[tid] = ov;
}

// ---------------- dense PPR iteration (fp8 S, half2 accumulate): X' = 0.8*A@X + 12.8*A ----------------
__global__ __launch_bounds__(256) void k_ppr_iter(int it) {
    const unsigned char* __restrict__ src = (it & 1) ? g_T8 : g_S8;
    unsigned char* __restrict__ dst       = (it & 1) ? g_S8 : g_T8;
    int r = blockIdx.x, tid = threadIdx.x;
    __shared__ int sj[KNN]; __shared__ float sw_[KNN];
    if (tid < KNN) { sj[tid] = g_ir[r * KNN + tid]; sw_[tid] = g_wr[r * KNN + tid]; }
    __syncthreads();
    int rj[KNN]; __half2 rw[KNN];
    #pragma unroll
    for (int t = 0; t < KNN; t++) { rj[t] = sj[t]; rw[t] = __float2half2_rn(sw_[t]); }

    const uint4* s4 = (const uint4*)src;   // 256 uint4 (4096 fp8) per row
    __half2 acc[8];
    #pragma unroll
    for (int e = 0; e < 8; e++) acc[e] = __float2half2_rn(0.f);
    #pragma unroll
    for (int t = 0; t < KNN; t++) {
        uint4 v = s4[(size_t)rj[t] * 256 + tid];
        const __nv_fp8x2_storage_t* pv = (const __nv_fp8x2_storage_t*)&v;
        #pragma unroll
        for (int e = 0; e < 8; e++) {
            __half2_raw hr = __nv_cvt_fp8x2_to_halfraw2(pv[e], __NV_E4M3);
            acc[e] = __hfma2(*(__half2*)&hr, rw[t], acc[e]);
        }
    }
    __half2 c08 = __float2half2_rn(0.8f);
    uint4 ov;
    __nv_fp8x2_storage_t* po = (__nv_fp8x2_storage_t*)&ov;
    #pragma unroll
    for (int e = 0; e < 8; e++) {
        __half2 o = __hmul2(acc[e], c08);
        po[e] = __nv_cvt_halfraw2_to_fp8x2(*(__half2_raw*)&o, __NV_SATFINITE, __NV_E4M3);
    }
    ((uint4*)(dst + (size_t)r * NPTS))[tid] = ov;
    __syncthreads();
    if (tid < KNN) {
        size_t p = (size_t)r * NPTS + sj[tid];
        __half_raw h = __nv_cvt_fp8_to_halfraw(dst[p], __NV_E4M3);
        float val = __half2float(*(__half*)&h) + 0.2f * PPR_SCALE * sw_[tid];
        dst[p] = __nv_cvt_float_to_fp8(val, __NV_SATFINITE, __NV_E4M3);
    }
}

// ---------------- last PPR iteration fused with diff stats (no S5 store) ----------------
__global__ __launch_bounds__(256) void k_ppr_last() {
    __shared__ float srow[NPTS];
    __shared__ float s1[256], s2[256];
    __shared__ int sj[KNN]; __shared__ float sw_[KNN];
    int r = blockIdx.x, tid = threadIdx.x;
    if (tid < KNN) { sj[tid] = g_ir[r * KNN + tid]; sw_[tid] = g_wr[r * KNN + tid]; }
    __syncthreads();
    int rj[KNN]; __half2 rw[KNN];
    #pragma unroll
    for (int t = 0; t < KNN; t++) { rj[t] = sj[t]; rw[t] = __float2half2_rn(sw_[t]); }

    const uint4* s4 = (const uint4*)g_T8;
    __half2 acc[8];
    #pragma unroll
    for (int e = 0; e < 8; e++) acc[e] = __float2half2_rn(0.f);
    #pragma unroll
    for (int t = 0; t < KNN; t++) {
        uint4 v = s4[(size_t)rj[t] * 256 + tid];
        const __nv_fp8x2_storage_t* pv = (const __nv_fp8x2_storage_t*)&v;
        #pragma unroll
        for (int e = 0; e < 8; e++) {
            __half2_raw hr = __nv_cvt_fp8x2_to_halfraw2(pv[e], __NV_E4M3);
            acc[e] = __hfma2(*(__half2*)&hr, rw[t], acc[e]);
        }
    }
    #pragma unroll
    for (int e = 0; e < 8; e++) {
        float2 f = __half22float2(acc[e]);
        srow[16 * tid + 2 * e]     = 0.8f * f.x;
        srow[16 * tid + 2 * e + 1] = 0.8f * f.y;
    }
    __syncthreads();
    if (tid < KNN) atomicAdd(&srow[sj[tid]], 0.2f * PPR_SCALE * sw_[tid]);
    __syncthreads();
    float sum = 0.f, sq = 0.f;
    #pragma unroll
    for (int e = 0; e < 16; e++) {
        float v = srow[16 * tid + e];
        sum += v; sq += v * v;
    }
    s1[tid] = sum; s2[tid] = sq;
    __syncthreads();
    for (int o = 128; o; o >>= 1) {
        if (tid < o) { s1[tid] += s1[tid + o]; s2[tid] += s2[tid + o]; }
        __syncthreads();
    }
    if (tid == 0) {
        float rs = s1[0] * (1.f / PPR_SCALE);
        float rq = s2[0] * (1.f / (PPR_SCALE * PPR_SCALE));
        float rinv = 1.f / fmaxf(rs, 1e-8f);
        float cross = 0.f, a2 = 0.f;
        for (int t = 0; t < KNN; t++) {
            int c = g_ia[r * KNN + t];
            float a = g_wa[r * KNN + t];
            cross += a * srow[c] * (1.f / PPR_SCALE);
            a2 += a * a;
        }
        double rowdiff = (double)rq * rinv * rinv - 2.0 * (double)rinv * (double)cross + (double)a2;
        atomicAdd(&g_acc[5], rowdiff);
    }
}

// ---------------- combine ----------------
__global__ void k_final(float* out) {
    double align = g_acc[0] / 4096.0;
    double attr  = g_acc[1] / 4096.0;
    double rep   = g_acc[2] / (4096.0 * 32.0);
    double lap   = (g_acc[4] - g_acc[3] / 15.0) / 4096.0;
    double diff  = g_acc[5] / (4096.0 * 4096.0);
    out[0] = (float)(align + (attr + rep) + 0.5 * lap + 0.5 * diff);
}

extern "C" void kernel_launch(void* const* d_in, const int* in_sizes, int n_in,
                              void* d_out, int out_size) {
    (void)in_sizes; (void)n_in; (void)out_size;
    const float* zr    = (const float*)d_in[0];
    const float* za    = (const float*)d_in[1];
    const float* noise = (const float*)d_in[2];
    float* out = (float*)d_out;

    const int SMEM_TOPK =
        (64 * QSTR + 64 * KSTR + 64 * KSTR + 64 * MXSTR) * (int)sizeof(float); // 93440 B
    cudaFuncSetAttribute(k_topk2, cudaFuncAttributeMaxDynamicSharedMemorySize, SMEM_TOPK);

    // fork/join resources: host-side handles only (not device memory).
    cudaStream_t s2;
    cudaStreamCreateWithFlags(&s2, cudaStreamNonBlocking);
    cudaEvent_t e1, e2;
    cudaEventCreateWithFlags(&e1, cudaEventDisableTiming);
    cudaEventCreateWithFlags(&e2, cudaEventDisableTiming);

    k_zero<<<1, 32>>>();                                 // launch 1
    k_norm<<<NPTS / 4, 128>>>(zr, za);                   // launch 2

    cudaEventRecord(e1, 0);
    cudaStreamWaitEvent(s2, e1, 0);

    k_topk2<<<dim3(64, 2, 2), 256, SMEM_TOPK>>>();       // launch 3 — fused both graphs
    k_negs_pre<<<NPTS, 256, 0, s2>>>(noise);             // launch 4 — profiled; overlaps topk2
    cudaEventRecord(e2, s2);

    k_topk_merge<<<32, 256>>>();                         // both graphs ready after this
    cudaStreamWaitEvent(0, e2, 0);                       // join: candidates ready
    k_negs_post<<<NPTS / 8, 256>>>();                    // exact negatives from candidates
    k_ppr_first<<<NPTS, 256>>>();                        // X1 -> g_S8
    for (int it = 0; it < 3; it++)                       // X2..X4
        k_ppr_iter<<<NPTS, 256>>>(it);                   // X4 -> g_T8
    k_ppr_last<<<NPTS, 256>>>();                         // X5 stats fused
    k_pair<<<NPTS / 8, 256>>>();                         // needs both graphs + negs
    k_final<<<1, 1>>>(out);
}